// round 1
// baseline (speedup 1.0000x reference)
#include <cuda_runtime.h>
#include <cuda_fp16.h>
#include <mma.h>

using namespace nvcuda;

// Problem constants (static shapes)
constexpr int HH   = 56;
constexpr int WWp  = 56;
constexpr int C    = 768;
constexpr int NH_  = 12;
constexpr int HD   = 64;
constexpr int WS_  = 14;
constexpr int N_   = 196;      // tokens per window
constexpr int NWIN = 256;      // 16 batch * 16 windows
constexpr int M_   = NWIN * N_;  // 50176 rows
constexpr int KQ   = 768;

// -------- device scratch (allocation-free rule: __device__ globals) --------
__device__ __half g_xh[(size_t)M_ * C];          // window-ordered fp16 x
__device__ __half g_wqkv[2304 * 768];
__device__ __half g_wproj[768 * 768];
__device__ float  g_bqkv[2304];
__device__ __half g_q[(size_t)NWIN * NH_ * N_ * HD];
__device__ __half g_k[(size_t)NWIN * NH_ * N_ * HD];
__device__ __half g_v[(size_t)NWIN * NH_ * N_ * HD];
__device__ float  g_rpb[(size_t)NH_ * N_ * N_];
__device__ __half g_ao[(size_t)M_ * C];          // attention output (proj input)

// ---------------------------------------------------------------------------
// prep kernels
// ---------------------------------------------------------------------------
__global__ void prep_w_kernel(const float* __restrict__ qkvw,
                              const float* __restrict__ projw,
                              const float* __restrict__ qb,
                              const float* __restrict__ vb) {
  int g = blockIdx.x * 256 + threadIdx.x;
  if (g < 2304 * 768) g_wqkv[g] = __float2half(qkvw[g]);
  if (g < 768 * 768)  g_wproj[g] = __float2half(projw[g]);
  if (g < 2304) g_bqkv[g] = (g < 768) ? qb[g] : ((g < 1536) ? 0.0f : vb[g - 1536]);
}

__global__ void rpb_kernel(const float* __restrict__ table) {
  int g = blockIdx.x * 256 + threadIdx.x;
  if (g >= N_ * N_) return;
  int a = g / N_, b = g - a * N_;
  int i1 = a / WS_, j1 = a - i1 * WS_;
  int i2 = b / WS_, j2 = b - i2 * WS_;
  int idx = (i1 - i2 + WS_ - 1) * (2 * WS_ - 1) + (j1 - j2 + WS_ - 1);
#pragma unroll
  for (int hh = 0; hh < NH_; hh++)
    g_rpb[(size_t)hh * N_ * N_ + g] = table[idx * NH_ + hh];
}

// x [B, H*W, C] fp32 -> g_xh [win*196, C] fp16 (window partition gather fused)
__global__ void convx_kernel(const float* __restrict__ x) {
  int g = blockIdx.x * 256 + threadIdx.x;     // exactly M_*96 threads, 8 elems each
  int m = g / 96, kk = g - m * 96;
  int w = m / N_, n = m - w * N_;
  int b = w >> 4, wr = w & 15, wh = wr >> 2, ww = wr & 3;
  int ii = n / WS_, jj = n - ii * WS_;
  size_t xr = (size_t)b * (HH * WWp) + (size_t)(wh * WS_ + ii) * WWp + (ww * WS_ + jj);
  const float4* src = (const float4*)(x + xr * C + kk * 8);
  float4 v0 = src[0], v1 = src[1];
  union { int4 i4; __half2 h2v[4]; } o;
  o.h2v[0] = __floats2half2_rn(v0.x, v0.y);
  o.h2v[1] = __floats2half2_rn(v0.z, v0.w);
  o.h2v[2] = __floats2half2_rn(v1.x, v1.y);
  o.h2v[3] = __floats2half2_rn(v1.z, v1.w);
  *(int4*)(g_xh + (size_t)m * C + kk * 8) = o.i4;
}

// ---------------------------------------------------------------------------
// WMMA GEMM: out[m, c] = sum_k A[m,k] * B[c,k] + bias[c]
// MODE 0: QKV (A=g_xh, B=g_wqkv, scatter to g_q/g_k/g_v, q scaled 0.125)
// MODE 1: proj (A=g_ao, B=g_wproj, scatter to d_out image layout)
// block tile 128x64, k-tile 32, 4 warps (each 64x32), double-buffered smem
// ---------------------------------------------------------------------------
template <int MODE>
__global__ __launch_bounds__(128) void gemm_kernel(const float* __restrict__ bias_in,
                                                   float* __restrict__ out_f) {
  constexpr int BM = 128, BN = 64, BK = 32, LDA = 40, LDB = 40, LDE = 68, NKT = KQ / BK;
  __shared__ __align__(16) union {
    struct { __half a[2][BM * LDA]; __half b[2][BN * LDB]; } s;
    float ep[BM * LDE];
  } sm;

  const __half* __restrict__ A = (MODE == 0) ? g_xh : g_ao;
  const __half* __restrict__ B = (MODE == 0) ? g_wqkv : g_wproj;
  const int m0 = blockIdx.y * BM;
  const int n0 = blockIdx.x * BN;
  const int tid = threadIdx.x;
  const int warp = tid >> 5;
  const int wy = warp >> 1, wx = warp & 1;

  wmma::fragment<wmma::accumulator, 16, 16, 16, float> acc[4][2];
#pragma unroll
  for (int i = 0; i < 4; i++)
#pragma unroll
    for (int j = 0; j < 2; j++) wmma::fill_fragment(acc[i][j], 0.0f);

  int4 ra[4], rb[2];
  auto ldg = [&](int kt) {
#pragma unroll
    for (int i = 0; i < 4; i++) {
      int p = tid + i * 128; int r = p >> 2, ko = (p & 3) << 3;
      ra[i] = *(const int4*)(A + (size_t)(m0 + r) * KQ + kt * BK + ko);
    }
#pragma unroll
    for (int i = 0; i < 2; i++) {
      int p = tid + i * 128; int r = p >> 2, ko = (p & 3) << 3;
      rb[i] = *(const int4*)(B + (size_t)(n0 + r) * KQ + kt * BK + ko);
    }
  };
  auto sts = [&](int buf) {
#pragma unroll
    for (int i = 0; i < 4; i++) {
      int p = tid + i * 128; int r = p >> 2, ko = (p & 3) << 3;
      *(int4*)&sm.s.a[buf][r * LDA + ko] = ra[i];
    }
#pragma unroll
    for (int i = 0; i < 2; i++) {
      int p = tid + i * 128; int r = p >> 2, ko = (p & 3) << 3;
      *(int4*)&sm.s.b[buf][r * LDB + ko] = rb[i];
    }
  };

  ldg(0); sts(0); __syncthreads();
  for (int kt = 0; kt < NKT; kt++) {
    if (kt + 1 < NKT) ldg(kt + 1);
    const int buf = kt & 1;
#pragma unroll
    for (int ks = 0; ks < 2; ks++) {
      wmma::fragment<wmma::matrix_a, 16, 16, 16, __half, wmma::row_major> af[4];
      wmma::fragment<wmma::matrix_b, 16, 16, 16, __half, wmma::col_major> bf[2];
#pragma unroll
      for (int i = 0; i < 4; i++)
        wmma::load_matrix_sync(af[i], &sm.s.a[buf][(wy * 64 + i * 16) * LDA + ks * 16], LDA);
#pragma unroll
      for (int j = 0; j < 2; j++)
        wmma::load_matrix_sync(bf[j], &sm.s.b[buf][(wx * 32 + j * 16) * LDB + ks * 16], LDB);
#pragma unroll
      for (int i = 0; i < 4; i++)
#pragma unroll
        for (int j = 0; j < 2; j++)
          wmma::mma_sync(acc[i][j], af[i], bf[j], acc[i][j]);
    }
    if (kt + 1 < NKT) sts((kt + 1) & 1);
    __syncthreads();
  }

  // epilogue: frags -> smem (union reuse) -> scatter
#pragma unroll
  for (int i = 0; i < 4; i++)
#pragma unroll
    for (int j = 0; j < 2; j++)
      wmma::store_matrix_sync(&sm.ep[(wy * 64 + i * 16) * LDE + wx * 32 + j * 16],
                              acc[i][j], LDE, wmma::mem_row_major);
  __syncthreads();
#pragma unroll 4
  for (int it = 0; it < 64; it++) {
    int idx = it * 128 + tid;
    int r = idx >> 6, cc = idx & 63;
    int m = m0 + r;
    int c = n0 + cc;
    float v = sm.ep[r * LDE + cc];
    int w = m / N_, n = m - w * N_;
    if (MODE == 0) {
      v += g_bqkv[c];
      int sec = c / 768, cu = c - sec * 768;
      int h = cu >> 6, d = cu & 63;
      size_t dst = ((size_t)(w * NH_ + h) * N_ + n) * HD + d;
      if (sec == 0)      g_q[dst] = __float2half(v * 0.125f);
      else if (sec == 1) g_k[dst] = __float2half(v);
      else               g_v[dst] = __float2half(v);
    } else {
      v += bias_in[c];
      int b = w >> 4, wr = w & 15, wh = wr >> 2, ww = wr & 3;
      int ii = n / WS_, jj = n - ii * WS_;
      size_t xr = (size_t)b * (HH * WWp) + (size_t)(wh * WS_ + ii) * WWp + (ww * WS_ + jj);
      out_f[xr * C + c] = v;
    }
  }
}

// ---------------------------------------------------------------------------
// attention: one block per (window, head, 64-row q chunk). K/V streamed in
// 32-key tiles. No max-subtraction (scores are tiny); normalizer from a
// ones-column appended to V (accumulator column 64). All static smem.
// ---------------------------------------------------------------------------
__global__ __launch_bounds__(128) void attn_kernel() {
  constexpr int LQ = 72, LK = 72, LV = 80, LS = 36, LP = 40, LO = 84;
  constexpr int KT = 32, NT = 7;  // 7*32 = 224 >= 196
  __shared__ __align__(16) __half Qs[64 * LQ];
  __shared__ __align__(16) union {
    struct { __half K[KT * LK]; __half V[KT * LV]; float S[64 * LS]; __half P[64 * LP]; } t;
    float O[64 * LO];
  } u;

  const int qc = blockIdx.x, h = blockIdx.y, w = blockIdx.z;
  const int tid = threadIdx.x, warp = tid >> 5;
  const size_t base = ((size_t)w * NH_ + h) * N_ * HD;
  const __half* Qg = g_q + base;
  const __half* Kg = g_k + base;
  const __half* Vg = g_v + base;

  // load Q chunk (64 rows, zero-pad past 196)
#pragma unroll
  for (int i = 0; i < 4; i++) {
    int p = tid + i * 128;
    int r = p >> 3, ko = (p & 7) << 3;
    int n = qc * 64 + r;
    int4 val = (n < N_) ? *(const int4*)(Qg + (size_t)n * HD + ko) : make_int4(0, 0, 0, 0);
    *(int4*)&Qs[r * LQ + ko] = val;
  }

  wmma::fragment<wmma::accumulator, 16, 16, 16, float> oacc[5];
#pragma unroll
  for (int c = 0; c < 5; c++) wmma::fill_fragment(oacc[c], 0.0f);
  __syncthreads();

  for (int t = 0; t < NT; t++) {
    // K,V tiles (32 rows)
#pragma unroll
    for (int i = 0; i < 2; i++) {
      int p = tid + i * 128;
      int r = p >> 3, ko = (p & 7) << 3;
      int jg = t * KT + r;
      int4 kv, vv;
      if (jg < N_) {
        kv = *(const int4*)(Kg + (size_t)jg * HD + ko);
        vv = *(const int4*)(Vg + (size_t)jg * HD + ko);
      } else { kv = make_int4(0, 0, 0, 0); vv = kv; }
      *(int4*)&u.t.K[r * LK + ko] = kv;
      *(int4*)&u.t.V[r * LV + ko] = vv;
    }
    // V extra columns 64..79: col 64 = 1 for valid keys (row-sum column)
    if (tid < KT) {
      int jg = t * KT + tid;
      __half one = __float2half(jg < N_ ? 1.0f : 0.0f);
#pragma unroll
      for (int co = 0; co < 16; co++)
        u.t.V[tid * LV + 64 + co] = (co == 0) ? one : __float2half(0.0f);
    }
    __syncthreads();

    // S = Q K^T (warp: rows [warp*16,+16), cols [0,32))
    {
      wmma::fragment<wmma::matrix_a, 16, 16, 16, __half, wmma::row_major> qa[4];
#pragma unroll
      for (int kk = 0; kk < 4; kk++)
        wmma::load_matrix_sync(qa[kk], &Qs[(warp * 16) * LQ + kk * 16], LQ);
#pragma unroll
      for (int j = 0; j < 2; j++) {
        wmma::fragment<wmma::accumulator, 16, 16, 16, float> sacc;
        wmma::fill_fragment(sacc, 0.0f);
#pragma unroll
        for (int kk = 0; kk < 4; kk++) {
          wmma::fragment<wmma::matrix_b, 16, 16, 16, __half, wmma::col_major> kb;
          wmma::load_matrix_sync(kb, &u.t.K[(j * 16) * LK + kk * 16], LK);
          wmma::mma_sync(sacc, qa[kk], kb, sacc);
        }
        wmma::store_matrix_sync(&u.t.S[(warp * 16) * LS + j * 16], sacc, LS, wmma::mem_row_major);
      }
    }
    __syncthreads();

    // P = exp(S + rpb), zero for padded rows/cols
#pragma unroll
    for (int i = 0; i < 16; i++) {
      int idx = i * 128 + tid;
      int r = idx >> 5, j = idx & 31;
      int n = qc * 64 + r, jg = t * KT + j;
      float val = 0.0f;
      if (n < N_ && jg < N_) {
        float s = u.t.S[r * LS + j] + g_rpb[((size_t)h * N_ + n) * N_ + jg];
        val = __expf(s);
      }
      u.t.P[r * LP + j] = __float2half(val);
    }
    __syncthreads();

    // O += P V (col frag 4 accumulates the row-sum normalizer)
    {
      wmma::fragment<wmma::matrix_a, 16, 16, 16, __half, wmma::row_major> pa[2];
#pragma unroll
      for (int kk = 0; kk < 2; kk++)
        wmma::load_matrix_sync(pa[kk], &u.t.P[(warp * 16) * LP + kk * 16], LP);
#pragma unroll
      for (int c = 0; c < 5; c++) {
#pragma unroll
        for (int kk = 0; kk < 2; kk++) {
          wmma::fragment<wmma::matrix_b, 16, 16, 16, __half, wmma::row_major> vb;
          wmma::load_matrix_sync(vb, &u.t.V[(kk * 16) * LV + c * 16], LV);
          wmma::mma_sync(oacc[c], pa[kk], vb, oacc[c]);
        }
      }
    }
    __syncthreads();
  }

  // normalize + write
#pragma unroll
  for (int c = 0; c < 5; c++)
    wmma::store_matrix_sync(&u.O[(warp * 16) * LO + c * 16], oacc[c], LO, wmma::mem_row_major);
  __syncthreads();
#pragma unroll
  for (int i = 0; i < 32; i++) {
    int idx = i * 128 + tid;
    int r = idx >> 6, d = idx & 63;
    int n = qc * 64 + r;
    if (n < N_) {
      float l = u.O[r * LO + 64];
      float o = u.O[r * LO + d] / l;
      g_ao[((size_t)w * N_ + n) * C + h * HD + d] = __float2half(o);
    }
  }
}

// ---------------------------------------------------------------------------
extern "C" void kernel_launch(void* const* d_in, const int* in_sizes, int n_in,
                              void* d_out, int out_size) {
  const float* x     = (const float*)d_in[0];
  const float* qkvw  = (const float*)d_in[1];
  const float* qb    = (const float*)d_in[2];
  const float* vb    = (const float*)d_in[3];
  const float* table = (const float*)d_in[4];
  const float* projw = (const float*)d_in[5];
  const float* projb = (const float*)d_in[6];
  float* out = (float*)d_out;
  (void)in_sizes; (void)n_in; (void)out_size;  // H=W=56 static

  prep_w_kernel<<<(2304 * 768) / 256, 256>>>(qkvw, projw, qb, vb);
  rpb_kernel<<<(N_ * N_ + 255) / 256, 256>>>(table);
  convx_kernel<<<(M_ * 96) / 256, 256>>>(x);
  gemm_kernel<0><<<dim3(2304 / 64, M_ / 128), 128>>>(nullptr, nullptr);
  attn_kernel<<<dim3(4, NH_, NWIN), 128>>>();
  gemm_kernel<1><<<dim3(768 / 64, M_ / 128), 128>>>(projb, out);
}

// round 3
// speedup vs baseline: 1.0173x; 1.0173x over previous
#include <cuda_runtime.h>
#include <cuda_fp16.h>
#include <mma.h>
#include <cstdint>

using namespace nvcuda;

// Problem constants (static shapes)
constexpr int HH   = 56;
constexpr int WWp  = 56;
constexpr int C    = 768;
constexpr int NH_  = 12;
constexpr int HD   = 64;
constexpr int WS_  = 14;
constexpr int N_   = 196;        // tokens per window
constexpr int NWIN = 256;        // 16 batch * 16 windows
constexpr int M_   = NWIN * N_;  // 50176 rows
constexpr int KQ   = 768;

// -------- device scratch (allocation-free rule: __device__ globals) --------
__device__ __half g_xh[(size_t)M_ * C];          // window-ordered fp16 x
__device__ __half g_wqkv[2304 * 768];
__device__ __half g_wproj[768 * 768];
__device__ float  g_bqkv[2304];
__device__ __half g_q[(size_t)NWIN * NH_ * N_ * HD];
__device__ __half g_k[(size_t)NWIN * NH_ * N_ * HD];
__device__ __half g_v[(size_t)NWIN * NH_ * N_ * HD];
__device__ float  g_rpb[(size_t)NH_ * N_ * N_];
__device__ __half g_ao[(size_t)M_ * C];          // attention output (proj input)

// ---------------------------------------------------------------------------
// prep kernels
// ---------------------------------------------------------------------------
__global__ void prep_w_kernel(const float* __restrict__ qkvw,
                              const float* __restrict__ projw,
                              const float* __restrict__ qb,
                              const float* __restrict__ vb) {
  int g = blockIdx.x * 256 + threadIdx.x;
  if (g < 2304 * 768) g_wqkv[g] = __float2half(qkvw[g]);
  if (g < 768 * 768)  g_wproj[g] = __float2half(projw[g]);
  if (g < 2304) g_bqkv[g] = (g < 768) ? qb[g] : ((g < 1536) ? 0.0f : vb[g - 1536]);
}

__global__ void rpb_kernel(const float* __restrict__ table) {
  int g = blockIdx.x * 256 + threadIdx.x;
  if (g >= N_ * N_) return;
  int a = g / N_, b = g - a * N_;
  int i1 = a / WS_, j1 = a - i1 * WS_;
  int i2 = b / WS_, j2 = b - i2 * WS_;
  int idx = (i1 - i2 + WS_ - 1) * (2 * WS_ - 1) + (j1 - j2 + WS_ - 1);
#pragma unroll
  for (int hh = 0; hh < NH_; hh++)
    g_rpb[(size_t)hh * N_ * N_ + g] = table[idx * NH_ + hh];
}

// x [B, H*W, C] fp32 -> g_xh [win*196, C] fp16 (window partition gather fused)
__global__ void convx_kernel(const float* __restrict__ x) {
  int g = blockIdx.x * 256 + threadIdx.x;
  int m = g / 96, kk = g - m * 96;
  int w = m / N_, n = m - w * N_;
  int b = w >> 4, wr = w & 15, wh = wr >> 2, ww = wr & 3;
  int ii = n / WS_, jj = n - ii * WS_;
  size_t xr = (size_t)b * (HH * WWp) + (size_t)(wh * WS_ + ii) * WWp + (ww * WS_ + jj);
  const float4* src = (const float4*)(x + xr * C + kk * 8);
  float4 v0 = src[0], v1 = src[1];
  union { int4 i4; __half2 h2v[4]; } o;
  o.h2v[0] = __floats2half2_rn(v0.x, v0.y);
  o.h2v[1] = __floats2half2_rn(v0.z, v0.w);
  o.h2v[2] = __floats2half2_rn(v1.x, v1.y);
  o.h2v[3] = __floats2half2_rn(v1.z, v1.w);
  *(int4*)(g_xh + (size_t)m * C + kk * 8) = o.i4;
}

// ---------------------------------------------------------------------------
// WMMA GEMM v2: out[m, c] = sum_k A[m,k] * B[c,k] + bias[c]
// CTA 256 thr, tile 128x256, warp tile 64x64 (4x4 wmma frags), k-step 32,
// 3-stage cp.async pipeline. Epilogue via smem in 2 phases of 128 cols.
// MODE 0: QKV (A=g_xh, B=g_wqkv -> g_q/g_k/g_v, q scaled 0.125)
// MODE 1: proj (A=g_ao, B=g_wproj -> d_out image layout)
// ---------------------------------------------------------------------------
template <int MODE>
__global__ __launch_bounds__(256) void gemm2_kernel(const float* __restrict__ bias_in,
                                                    float* __restrict__ out_f) {
  constexpr int BM = 128, BN = 256, BK = 32, S = 3;
  constexpr int LDA = 40, LDB = 40, LDE = 132;
  constexpr int NKT = KQ / BK;                       // 24
  constexpr int ABYTES = BM * LDA * 2;               // 10240
  constexpr int BBYTES = BN * LDB * 2;               // 20480
  constexpr int STG = ABYTES + BBYTES;               // 30720

  extern __shared__ __align__(16) char dsm[];
  __half* sa = (__half*)dsm;                         // [S][BM*LDA] at slot*STG
  float*  ep = (float*)dsm;                          // epilogue reuse

  const __half* __restrict__ A  = (MODE == 0) ? g_xh : g_ao;
  const __half* __restrict__ Bw = (MODE == 0) ? g_wqkv : g_wproj;
  const int n0 = blockIdx.x * BN;
  const int m0 = blockIdx.y * BM;
  const int tid = threadIdx.x;
  const int warp = tid >> 5;
  const int wm = warp >> 2, wn = warp & 3;           // 2 x 4 warp grid

  wmma::fragment<wmma::accumulator, 16, 16, 16, float> acc[4][4];
#pragma unroll
  for (int i = 0; i < 4; i++)
#pragma unroll
    for (int j = 0; j < 4; j++) wmma::fill_fragment(acc[i][j], 0.0f);

  auto load_stage = [&](int kt) {
    const int slot = kt % S;
    char* abase = dsm + slot * STG;
    char* bbase = abase + ABYTES;
    const char* ag = (const char*)(A + (size_t)m0 * KQ + kt * BK);
    const char* bg = (const char*)(Bw + (size_t)n0 * KQ + kt * BK);
#pragma unroll
    for (int i = 0; i < 2; i++) {                    // A: 128 rows x 64B
      int q = tid + i * 256; int r = q >> 2, co = q & 3;
      uint32_t so = (uint32_t)(size_t)(abase + r * (LDA * 2) + co * 16);
      asm volatile("{ .reg .u64 t; cvta.to.shared.u64 t, %0; .reg .u32 s; cvt.u32.u64 s, t;"
                   " cp.async.cg.shared.global [s], [%1], 16; }"
                   :: "l"(abase + r * (LDA * 2) + co * 16),
                      "l"(ag + (size_t)r * (KQ * 2) + co * 16) : "memory");
      (void)so;
    }
#pragma unroll
    for (int i = 0; i < 4; i++) {                    // B: 256 rows x 64B
      int q = tid + i * 256; int r = q >> 2, co = q & 3;
      asm volatile("{ .reg .u64 t; cvta.to.shared.u64 t, %0; .reg .u32 s; cvt.u32.u64 s, t;"
                   " cp.async.cg.shared.global [s], [%1], 16; }"
                   :: "l"(bbase + r * (LDB * 2) + co * 16),
                      "l"(bg + (size_t)r * (KQ * 2) + co * 16) : "memory");
    }
    asm volatile("cp.async.commit_group;" ::: "memory");
  };

  load_stage(0);
  load_stage(1);

  for (int kt = 0; kt < NKT; kt++) {
    if (kt == NKT - 1) asm volatile("cp.async.wait_group 0;" ::: "memory");
    else               asm volatile("cp.async.wait_group 1;" ::: "memory");
    __syncthreads();
    if (kt + 2 < NKT) load_stage(kt + 2);

    const int slot = kt % S;
    const __half* sA = (const __half*)(dsm + slot * STG);
    const __half* sB = (const __half*)(dsm + slot * STG + ABYTES);
#pragma unroll
    for (int ks = 0; ks < 2; ks++) {
      wmma::fragment<wmma::matrix_a, 16, 16, 16, __half, wmma::row_major> af[4];
      wmma::fragment<wmma::matrix_b, 16, 16, 16, __half, wmma::col_major> bf[4];
#pragma unroll
      for (int i = 0; i < 4; i++)
        wmma::load_matrix_sync(af[i], &sA[(wm * 64 + i * 16) * LDA + ks * 16], LDA);
#pragma unroll
      for (int j = 0; j < 4; j++)
        wmma::load_matrix_sync(bf[j], &sB[(wn * 64 + j * 16) * LDB + ks * 16], LDB);
#pragma unroll
      for (int i = 0; i < 4; i++)
#pragma unroll
        for (int j = 0; j < 4; j++)
          wmma::mma_sync(acc[i][j], af[i], bf[j], acc[i][j]);
    }
    __syncthreads();
  }

  // epilogue: 2 phases x 128 cols through smem, fused bias + scatter
#pragma unroll 1
  for (int p = 0; p < 2; p++) {
    if ((wn >> 1) == p) {
#pragma unroll
      for (int i = 0; i < 4; i++)
#pragma unroll
        for (int j = 0; j < 4; j++)
          wmma::store_matrix_sync(&ep[(wm * 64 + i * 16) * LDE + (wn & 1) * 64 + j * 16],
                                  acc[i][j], LDE, wmma::mem_row_major);
    }
    __syncthreads();
#pragma unroll 4
    for (int it = 0; it < 64; it++) {
      int idx = it * 256 + tid;                      // 128x128 elements
      int r = idx >> 7, cc = idx & 127;
      int m = m0 + r;
      int c = n0 + p * 128 + cc;
      float v = ep[r * LDE + cc];
      int w = m / N_, n = m - w * N_;
      if (MODE == 0) {
        v += g_bqkv[c];
        int sec = c / 768, cu = c - sec * 768;
        int h = cu >> 6, d = cu & 63;
        size_t dst = ((size_t)(w * NH_ + h) * N_ + n) * HD + d;
        if (sec == 0)      g_q[dst] = __float2half(v * 0.125f);
        else if (sec == 1) g_k[dst] = __float2half(v);
        else               g_v[dst] = __float2half(v);
      } else {
        v += bias_in[c];
        int b = w >> 4, wr = w & 15, wh = wr >> 2, ww = wr & 3;
        int ii = n / WS_, jj = n - ii * WS_;
        size_t xr = (size_t)b * (HH * WWp) + (size_t)(wh * WS_ + ii) * WWp + (ww * WS_ + jj);
        out_f[xr * C + c] = v;
      }
    }
    __syncthreads();
  }
}

// ---------------------------------------------------------------------------
// attention: one block per (window, head, 64-row q chunk). K/V streamed in
// 32-key tiles. No max-subtraction (scores tiny); normalizer via ones-col in V.
// ---------------------------------------------------------------------------
__global__ __launch_bounds__(128) void attn_kernel() {
  constexpr int LQ = 72, LK = 72, LV = 80, LS = 36, LP = 40, LO = 84;
  constexpr int KT = 32, NT = 7;
  __shared__ __align__(16) __half Qs[64 * LQ];
  __shared__ __align__(16) union {
    struct { __half K[KT * LK]; __half V[KT * LV]; float S[64 * LS]; __half P[64 * LP]; } t;
    float O[64 * LO];
  } u;

  const int qc = blockIdx.x, h = blockIdx.y, w = blockIdx.z;
  const int tid = threadIdx.x, warp = tid >> 5;
  const size_t base = ((size_t)w * NH_ + h) * N_ * HD;
  const __half* Qg = g_q + base;
  const __half* Kg = g_k + base;
  const __half* Vg = g_v + base;

#pragma unroll
  for (int i = 0; i < 4; i++) {
    int p = tid + i * 128;
    int r = p >> 3, ko = (p & 7) << 3;
    int n = qc * 64 + r;
    int4 val = (n < N_) ? *(const int4*)(Qg + (size_t)n * HD + ko) : make_int4(0, 0, 0, 0);
    *(int4*)&Qs[r * LQ + ko] = val;
  }

  wmma::fragment<wmma::accumulator, 16, 16, 16, float> oacc[5];
#pragma unroll
  for (int c = 0; c < 5; c++) wmma::fill_fragment(oacc[c], 0.0f);
  __syncthreads();

  for (int t = 0; t < NT; t++) {
#pragma unroll
    for (int i = 0; i < 2; i++) {
      int p = tid + i * 128;
      int r = p >> 3, ko = (p & 7) << 3;
      int jg = t * KT + r;
      int4 kv, vv;
      if (jg < N_) {
        kv = *(const int4*)(Kg + (size_t)jg * HD + ko);
        vv = *(const int4*)(Vg + (size_t)jg * HD + ko);
      } else { kv = make_int4(0, 0, 0, 0); vv = kv; }
      *(int4*)&u.t.K[r * LK + ko] = kv;
      *(int4*)&u.t.V[r * LV + ko] = vv;
    }
    if (tid < KT) {
      int jg = t * KT + tid;
      __half one = __float2half(jg < N_ ? 1.0f : 0.0f);
#pragma unroll
      for (int co = 0; co < 16; co++)
        u.t.V[tid * LV + 64 + co] = (co == 0) ? one : __float2half(0.0f);
    }
    __syncthreads();

    {
      wmma::fragment<wmma::matrix_a, 16, 16, 16, __half, wmma::row_major> qa[4];
#pragma unroll
      for (int kk = 0; kk < 4; kk++)
        wmma::load_matrix_sync(qa[kk], &Qs[(warp * 16) * LQ + kk * 16], LQ);
#pragma unroll
      for (int j = 0; j < 2; j++) {
        wmma::fragment<wmma::accumulator, 16, 16, 16, float> sacc;
        wmma::fill_fragment(sacc, 0.0f);
#pragma unroll
        for (int kk = 0; kk < 4; kk++) {
          wmma::fragment<wmma::matrix_b, 16, 16, 16, __half, wmma::col_major> kb;
          wmma::load_matrix_sync(kb, &u.t.K[(j * 16) * LK + kk * 16], LK);
          wmma::mma_sync(sacc, qa[kk], kb, sacc);
        }
        wmma::store_matrix_sync(&u.t.S[(warp * 16) * LS + j * 16], sacc, LS, wmma::mem_row_major);
      }
    }
    __syncthreads();

#pragma unroll
    for (int i = 0; i < 16; i++) {
      int idx = i * 128 + tid;
      int r = idx >> 5, j = idx & 31;
      int n = qc * 64 + r, jg = t * KT + j;
      float val = 0.0f;
      if (n < N_ && jg < N_) {
        float s = u.t.S[r * LS + j] + g_rpb[((size_t)h * N_ + n) * N_ + jg];
        val = __expf(s);
      }
      u.t.P[r * LP + j] = __float2half(val);
    }
    __syncthreads();

    {
      wmma::fragment<wmma::matrix_a, 16, 16, 16, __half, wmma::row_major> pa[2];
#pragma unroll
      for (int kk = 0; kk < 2; kk++)
        wmma::load_matrix_sync(pa[kk], &u.t.P[(warp * 16) * LP + kk * 16], LP);
#pragma unroll
      for (int c = 0; c < 5; c++) {
#pragma unroll
        for (int kk = 0; kk < 2; kk++) {
          wmma::fragment<wmma::matrix_b, 16, 16, 16, __half, wmma::row_major> vb;
          wmma::load_matrix_sync(vb, &u.t.V[(kk * 16) * LV + c * 16], LV);
          wmma::mma_sync(oacc[c], pa[kk], vb, oacc[c]);
        }
      }
    }
    __syncthreads();
  }

#pragma unroll
  for (int c = 0; c < 5; c++)
    wmma::store_matrix_sync(&u.O[(warp * 16) * LO + c * 16], oacc[c], LO, wmma::mem_row_major);
  __syncthreads();
#pragma unroll
  for (int i = 0; i < 32; i++) {
    int idx = i * 128 + tid;
    int r = idx >> 6, d = idx & 63;
    int n = qc * 64 + r;
    if (n < N_) {
      float l = u.O[r * LO + 64];
      float o = u.O[r * LO + d] / l;
      g_ao[((size_t)w * N_ + n) * C + h * HD + d] = __float2half(o);
    }
  }
}

// ---------------------------------------------------------------------------
extern "C" void kernel_launch(void* const* d_in, const int* in_sizes, int n_in,
                              void* d_out, int out_size) {
  const float* x     = (const float*)d_in[0];
  const float* qkvw  = (const float*)d_in[1];
  const float* qb    = (const float*)d_in[2];
  const float* vb    = (const float*)d_in[3];
  const float* table = (const float*)d_in[4];
  const float* projw = (const float*)d_in[5];
  const float* projb = (const float*)d_in[6];
  float* out = (float*)d_out;
  (void)in_sizes; (void)n_in; (void)out_size;

  const int DSMEM = 3 * (128 * 40 * 2 + 256 * 40 * 2);  // 92160 B (> epilogue 67584)
  cudaFuncSetAttribute(gemm2_kernel<0>, cudaFuncAttributeMaxDynamicSharedMemorySize, DSMEM);
  cudaFuncSetAttribute(gemm2_kernel<1>, cudaFuncAttributeMaxDynamicSharedMemorySize, DSMEM);

  prep_w_kernel<<<(2304 * 768) / 256, 256>>>(qkvw, projw, qb, vb);
  rpb_kernel<<<(N_ * N_ + 255) / 256, 256>>>(table);
  convx_kernel<<<(M_ * 96) / 256, 256>>>(x);
  gemm2_kernel<0><<<dim3(2304 / 256, M_ / 128), 256, DSMEM>>>(nullptr, nullptr);
  attn_kernel<<<dim3(4, NH_, NWIN), 128>>>();
  gemm2_kernel<1><<<dim3(768 / 256, M_ / 128), 256, DSMEM>>>(projb, out);
}

// round 4
// speedup vs baseline: 1.2172x; 1.1965x over previous
#include <cuda_runtime.h>
#include <cuda_fp16.h>
#include <mma.h>
#include <cstdint>

using namespace nvcuda;

// Problem constants (static shapes)
constexpr int HH   = 56;
constexpr int WWp  = 56;
constexpr int C    = 768;
constexpr int NH_  = 12;
constexpr int HD   = 64;
constexpr int WS_  = 14;
constexpr int N_   = 196;        // tokens per window
constexpr int NWIN = 256;        // 16 batch * 16 windows
constexpr int M_   = NWIN * N_;  // 50176 rows
constexpr int KQ   = 768;

// -------- device scratch (allocation-free rule: __device__ globals) --------
__device__ __half g_xh[(size_t)M_ * C];          // window-ordered fp16 x
__device__ __half g_wqkv[2304 * 768];
__device__ __half g_wproj[768 * 768];
__device__ float  g_bqkv[2304];
__device__ __half g_q[(size_t)NWIN * NH_ * N_ * HD];
__device__ __half g_k[(size_t)NWIN * NH_ * N_ * HD];
__device__ __half g_v[(size_t)NWIN * NH_ * N_ * HD];
__device__ float  g_rpb[(size_t)NH_ * N_ * N_];
__device__ __half g_ao[(size_t)M_ * C];          // attention output (proj input)

// ---------------------------------------------------------------------------
// prep kernels
// ---------------------------------------------------------------------------
__global__ void prep_w_kernel(const float* __restrict__ qkvw,
                              const float* __restrict__ projw,
                              const float* __restrict__ qb,
                              const float* __restrict__ vb) {
  int g = blockIdx.x * 256 + threadIdx.x;
  if (g < 2304 * 768) g_wqkv[g] = __float2half(qkvw[g]);
  if (g < 768 * 768)  g_wproj[g] = __float2half(projw[g]);
  if (g < 2304) g_bqkv[g] = (g < 768) ? qb[g] : ((g < 1536) ? 0.0f : vb[g - 1536]);
}

__global__ void rpb_kernel(const float* __restrict__ table) {
  int g = blockIdx.x * 256 + threadIdx.x;
  if (g >= N_ * N_) return;
  int a = g / N_, b = g - a * N_;
  int i1 = a / WS_, j1 = a - i1 * WS_;
  int i2 = b / WS_, j2 = b - i2 * WS_;
  int idx = (i1 - i2 + WS_ - 1) * (2 * WS_ - 1) + (j1 - j2 + WS_ - 1);
#pragma unroll
  for (int hh = 0; hh < NH_; hh++)
    g_rpb[(size_t)hh * N_ * N_ + g] = table[idx * NH_ + hh];
}

// x [B, H*W, C] fp32 -> g_xh [win*196, C] fp16 (window partition gather fused)
__global__ void convx_kernel(const float* __restrict__ x) {
  int g = blockIdx.x * 256 + threadIdx.x;
  int m = g / 96, kk = g - m * 96;
  int w = m / N_, n = m - w * N_;
  int b = w >> 4, wr = w & 15, wh = wr >> 2, ww = wr & 3;
  int ii = n / WS_, jj = n - ii * WS_;
  size_t xr = (size_t)b * (HH * WWp) + (size_t)(wh * WS_ + ii) * WWp + (ww * WS_ + jj);
  const float4* src = (const float4*)(x + xr * C + kk * 8);
  float4 v0 = src[0], v1 = src[1];
  union { int4 i4; __half2 h2v[4]; } o;
  o.h2v[0] = __floats2half2_rn(v0.x, v0.y);
  o.h2v[1] = __floats2half2_rn(v0.z, v0.w);
  o.h2v[2] = __floats2half2_rn(v1.x, v1.y);
  o.h2v[3] = __floats2half2_rn(v1.z, v1.w);
  *(int4*)(g_xh + (size_t)m * C + kk * 8) = o.i4;
}

// ---------------------------------------------------------------------------
// WMMA GEMM v3: out[m, c] = sum_k A[m,k] * B[c,k] + bias[c]
// CTA 256 thr, tile 128x128, warp tile 32x64 (2x4 wmma frags), k-step 32,
// 3-stage cp.async pipeline, __launch_bounds__(256,2) -> 2 CTAs/SM resident
// so one CTA's MMA covers the other's barrier/load latency bubbles.
// MODE 0: QKV (A=g_xh, B=g_wqkv -> g_q/g_k/g_v, q scaled 0.125)
// MODE 1: proj (A=g_ao, B=g_wproj -> d_out image layout)
// ---------------------------------------------------------------------------
template <int MODE>
__global__ __launch_bounds__(256, 2) void gemm3_kernel(const float* __restrict__ bias_in,
                                                       float* __restrict__ out_f) {
  constexpr int BM = 128, BN = 128, BK = 32, S = 3;
  constexpr int LDA = 40, LDB = 40, LDE = 132;
  constexpr int NKT = KQ / BK;                       // 24
  constexpr int ABYTES = BM * LDA * 2;               // 10240
  constexpr int BBYTES = BN * LDB * 2;               // 10240
  constexpr int STG = ABYTES + BBYTES;               // 20480

  extern __shared__ __align__(16) char dsm[];
  float* ep = (float*)dsm;                           // epilogue reuse

  const __half* __restrict__ A  = (MODE == 0) ? g_xh : g_ao;
  const __half* __restrict__ Bw = (MODE == 0) ? g_wqkv : g_wproj;
  const int n0 = blockIdx.x * BN;
  const int m0 = blockIdx.y * BM;
  const int tid = threadIdx.x;
  const int warp = tid >> 5;
  const int wm = warp >> 1, wn = warp & 1;           // 4 x 2 warp grid

  wmma::fragment<wmma::accumulator, 16, 16, 16, float> acc[2][4];
#pragma unroll
  for (int i = 0; i < 2; i++)
#pragma unroll
    for (int j = 0; j < 4; j++) wmma::fill_fragment(acc[i][j], 0.0f);

  auto load_stage = [&](int kt) {
    const int slot = kt % S;
    char* abase = dsm + slot * STG;
    char* bbase = abase + ABYTES;
    const char* ag = (const char*)(A + (size_t)m0 * KQ + kt * BK);
    const char* bg = (const char*)(Bw + (size_t)n0 * KQ + kt * BK);
#pragma unroll
    for (int i = 0; i < 2; i++) {                    // A: 128 rows x 64B
      int q = tid + i * 256; int r = q >> 2, co = q & 3;
      asm volatile("{ .reg .u64 t; cvta.to.shared.u64 t, %0; .reg .u32 s; cvt.u32.u64 s, t;"
                   " cp.async.cg.shared.global [s], [%1], 16; }"
                   :: "l"(abase + r * (LDA * 2) + co * 16),
                      "l"(ag + (size_t)r * (KQ * 2) + co * 16) : "memory");
    }
#pragma unroll
    for (int i = 0; i < 2; i++) {                    // B: 128 rows x 64B
      int q = tid + i * 256; int r = q >> 2, co = q & 3;
      asm volatile("{ .reg .u64 t; cvta.to.shared.u64 t, %0; .reg .u32 s; cvt.u32.u64 s, t;"
                   " cp.async.cg.shared.global [s], [%1], 16; }"
                   :: "l"(bbase + r * (LDB * 2) + co * 16),
                      "l"(bg + (size_t)r * (KQ * 2) + co * 16) : "memory");
    }
    asm volatile("cp.async.commit_group;" ::: "memory");
  };

  load_stage(0);
  load_stage(1);

  for (int kt = 0; kt < NKT; kt++) {
    if (kt == NKT - 1) asm volatile("cp.async.wait_group 0;" ::: "memory");
    else               asm volatile("cp.async.wait_group 1;" ::: "memory");
    __syncthreads();
    if (kt + 2 < NKT) load_stage(kt + 2);

    const int slot = kt % S;
    const __half* sA = (const __half*)(dsm + slot * STG);
    const __half* sB = (const __half*)(dsm + slot * STG + ABYTES);
#pragma unroll
    for (int ks = 0; ks < 2; ks++) {
      wmma::fragment<wmma::matrix_a, 16, 16, 16, __half, wmma::row_major> af[2];
      wmma::fragment<wmma::matrix_b, 16, 16, 16, __half, wmma::col_major> bf[4];
#pragma unroll
      for (int i = 0; i < 2; i++)
        wmma::load_matrix_sync(af[i], &sA[(wm * 32 + i * 16) * LDA + ks * 16], LDA);
#pragma unroll
      for (int j = 0; j < 4; j++)
        wmma::load_matrix_sync(bf[j], &sB[(wn * 64 + j * 16) * LDB + ks * 16], LDB);
#pragma unroll
      for (int i = 0; i < 2; i++)
#pragma unroll
        for (int j = 0; j < 4; j++)
          wmma::mma_sync(acc[i][j], af[i], bf[j], acc[i][j]);
    }
    __syncthreads();
  }

  // epilogue: all frags -> smem -> fused bias + vectorized scatter
  __syncthreads();
#pragma unroll
  for (int i = 0; i < 2; i++)
#pragma unroll
    for (int j = 0; j < 4; j++)
      wmma::store_matrix_sync(&ep[(wm * 32 + i * 16) * LDE + wn * 64 + j * 16],
                              acc[i][j], LDE, wmma::mem_row_major);
  __syncthreads();
#pragma unroll 4
  for (int it = 0; it < 32; it++) {                  // 128x128 / 2 = 8192 pairs
    int idx = it * 256 + tid;
    int r = idx >> 6, ccp = idx & 63;
    int cc = ccp * 2;
    int m = m0 + r;
    int c = n0 + cc;
    float v0 = ep[r * LDE + cc];
    float v1 = ep[r * LDE + cc + 1];
    int w = m / N_, n = m - w * N_;
    if (MODE == 0) {
      v0 += g_bqkv[c];
      v1 += g_bqkv[c + 1];
      int sec = c / 768, cu = c - sec * 768;
      int h = cu >> 6, d = cu & 63;                  // pair stays within one head
      __half* dst = ((sec == 0) ? g_q : (sec == 1) ? g_k : g_v) +
                    ((size_t)(w * NH_ + h) * N_ + n) * HD + d;
      float sc = (sec == 0) ? 0.125f : 1.0f;
      *(__half2*)dst = __floats2half2_rn(v0 * sc, v1 * sc);
    } else {
      v0 += bias_in[c];
      v1 += bias_in[c + 1];
      int b = w >> 4, wr = w & 15, wh = wr >> 2, ww = wr & 3;
      int ii = n / WS_, jj = n - ii * WS_;
      size_t xr = (size_t)b * (HH * WWp) + (size_t)(wh * WS_ + ii) * WWp + (ww * WS_ + jj);
      *(float2*)(out_f + xr * C + c) = make_float2(v0, v1);
    }
  }
}

// ---------------------------------------------------------------------------
// attention: one block per (window, head, 64-row q chunk). K/V streamed in
// 32-key tiles. No max-subtraction (scores tiny); normalizer via ones-col in V.
// ---------------------------------------------------------------------------
__global__ __launch_bounds__(128) void attn_kernel() {
  constexpr int LQ = 72, LK = 72, LV = 80, LS = 36, LP = 40, LO = 84;
  constexpr int KT = 32, NT = 7;
  __shared__ __align__(16) __half Qs[64 * LQ];
  __shared__ __align__(16) union {
    struct { __half K[KT * LK]; __half V[KT * LV]; float S[64 * LS]; __half P[64 * LP]; } t;
    float O[64 * LO];
  } u;

  const int qc = blockIdx.x, h = blockIdx.y, w = blockIdx.z;
  const int tid = threadIdx.x, warp = tid >> 5;
  const size_t base = ((size_t)w * NH_ + h) * N_ * HD;
  const __half* Qg = g_q + base;
  const __half* Kg = g_k + base;
  const __half* Vg = g_v + base;

#pragma unroll
  for (int i = 0; i < 4; i++) {
    int p = tid + i * 128;
    int r = p >> 3, ko = (p & 7) << 3;
    int n = qc * 64 + r;
    int4 val = (n < N_) ? *(const int4*)(Qg + (size_t)n * HD + ko) : make_int4(0, 0, 0, 0);
    *(int4*)&Qs[r * LQ + ko] = val;
  }

  wmma::fragment<wmma::accumulator, 16, 16, 16, float> oacc[5];
#pragma unroll
  for (int c = 0; c < 5; c++) wmma::fill_fragment(oacc[c], 0.0f);
  __syncthreads();

  for (int t = 0; t < NT; t++) {
#pragma unroll
    for (int i = 0; i < 2; i++) {
      int p = tid + i * 128;
      int r = p >> 3, ko = (p & 7) << 3;
      int jg = t * KT + r;
      int4 kv, vv;
      if (jg < N_) {
        kv = *(const int4*)(Kg + (size_t)jg * HD + ko);
        vv = *(const int4*)(Vg + (size_t)jg * HD + ko);
      } else { kv = make_int4(0, 0, 0, 0); vv = kv; }
      *(int4*)&u.t.K[r * LK + ko] = kv;
      *(int4*)&u.t.V[r * LV + ko] = vv;
    }
    if (tid < KT) {
      int jg = t * KT + tid;
      __half one = __float2half(jg < N_ ? 1.0f : 0.0f);
#pragma unroll
      for (int co = 0; co < 16; co++)
        u.t.V[tid * LV + 64 + co] = (co == 0) ? one : __float2half(0.0f);
    }
    __syncthreads();

    {
      wmma::fragment<wmma::matrix_a, 16, 16, 16, __half, wmma::row_major> qa[4];
#pragma unroll
      for (int kk = 0; kk < 4; kk++)
        wmma::load_matrix_sync(qa[kk], &Qs[(warp * 16) * LQ + kk * 16], LQ);
#pragma unroll
      for (int j = 0; j < 2; j++) {
        wmma::fragment<wmma::accumulator, 16, 16, 16, float> sacc;
        wmma::fill_fragment(sacc, 0.0f);
#pragma unroll
        for (int kk = 0; kk < 4; kk++) {
          wmma::fragment<wmma::matrix_b, 16, 16, 16, __half, wmma::col_major> kb;
          wmma::load_matrix_sync(kb, &u.t.K[(j * 16) * LK + kk * 16], LK);
          wmma::mma_sync(sacc, qa[kk], kb, sacc);
        }
        wmma::store_matrix_sync(&u.t.S[(warp * 16) * LS + j * 16], sacc, LS, wmma::mem_row_major);
      }
    }
    __syncthreads();

#pragma unroll
    for (int i = 0; i < 16; i++) {
      int idx = i * 128 + tid;
      int r = idx >> 5, j = idx & 31;
      int n = qc * 64 + r, jg = t * KT + j;
      float val = 0.0f;
      if (n < N_ && jg < N_) {
        float s = u.t.S[r * LS + j] + g_rpb[((size_t)h * N_ + n) * N_ + jg];
        val = __expf(s);
      }
      u.t.P[r * LP + j] = __float2half(val);
    }
    __syncthreads();

    {
      wmma::fragment<wmma::matrix_a, 16, 16, 16, __half, wmma::row_major> pa[2];
#pragma unroll
      for (int kk = 0; kk < 2; kk++)
        wmma::load_matrix_sync(pa[kk], &u.t.P[(warp * 16) * LP + kk * 16], LP);
#pragma unroll
      for (int c = 0; c < 5; c++) {
#pragma unroll
        for (int kk = 0; kk < 2; kk++) {
          wmma::fragment<wmma::matrix_b, 16, 16, 16, __half, wmma::row_major> vb;
          wmma::load_matrix_sync(vb, &u.t.V[(kk * 16) * LV + c * 16], LV);
          wmma::mma_sync(oacc[c], pa[kk], vb, oacc[c]);
        }
      }
    }
    __syncthreads();
  }

#pragma unroll
  for (int c = 0; c < 5; c++)
    wmma::store_matrix_sync(&u.O[(warp * 16) * LO + c * 16], oacc[c], LO, wmma::mem_row_major);
  __syncthreads();
#pragma unroll
  for (int i = 0; i < 32; i++) {
    int idx = i * 128 + tid;
    int r = idx >> 6, d = idx & 63;
    int n = qc * 64 + r;
    if (n < N_) {
      float l = u.O[r * LO + 64];
      float o = u.O[r * LO + d] / l;
      g_ao[((size_t)w * N_ + n) * C + h * HD + d] = __float2half(o);
    }
  }
}

// ---------------------------------------------------------------------------
extern "C" void kernel_launch(void* const* d_in, const int* in_sizes, int n_in,
                              void* d_out, int out_size) {
  const float* x     = (const float*)d_in[0];
  const float* qkvw  = (const float*)d_in[1];
  const float* qb    = (const float*)d_in[2];
  const float* vb    = (const float*)d_in[3];
  const float* table = (const float*)d_in[4];
  const float* projw = (const float*)d_in[5];
  const float* projb = (const float*)d_in[6];
  float* out = (float*)d_out;
  (void)in_sizes; (void)n_in; (void)out_size;

  // max(3 stages = 61440, epilogue 128*132*4 = 67584)
  const int DSMEM = 128 * 132 * 4;
  cudaFuncSetAttribute(gemm3_kernel<0>, cudaFuncAttributeMaxDynamicSharedMemorySize, DSMEM);
  cudaFuncSetAttribute(gemm3_kernel<1>, cudaFuncAttributeMaxDynamicSharedMemorySize, DSMEM);

  prep_w_kernel<<<(2304 * 768) / 256, 256>>>(qkvw, projw, qb, vb);
  rpb_kernel<<<(N_ * N_ + 255) / 256, 256>>>(table);
  convx_kernel<<<(M_ * 96) / 256, 256>>>(x);
  gemm3_kernel<0><<<dim3(2304 / 128, M_ / 128), 256, DSMEM>>>(nullptr, nullptr);
  attn_kernel<<<dim3(4, NH_, NWIN), 128>>>();
  gemm3_kernel<1><<<dim3(768 / 128, M_ / 128), 256, DSMEM>>>(projb, out);
}

// round 5
// speedup vs baseline: 1.2565x; 1.0323x over previous
#include <cuda_runtime.h>
#include <cuda_fp16.h>
#include <mma.h>
#include <cstdint>

using namespace nvcuda;

// Problem constants (static shapes)
constexpr int HH   = 56;
constexpr int WWp  = 56;
constexpr int C    = 768;
constexpr int NH_  = 12;
constexpr int HD   = 64;
constexpr int WS_  = 14;
constexpr int N_   = 196;        // tokens per window
constexpr int NWIN = 256;        // 16 batch * 16 windows
constexpr int M_   = NWIN * N_;  // 50176 rows
constexpr int KQ   = 768;
constexpr int RLD  = 200;        // padded rpb row stride (halfs), 400B = 25 int4

// -------- device scratch (allocation-free rule: __device__ globals) --------
__device__ __half g_xh[(size_t)M_ * C];          // window-ordered fp16 x
__device__ __half g_wqkv[2304 * 768];
__device__ __half g_wproj[768 * 768];
__device__ float  g_bqkv[2304];
__device__ __half g_q[(size_t)NWIN * NH_ * N_ * HD];
__device__ __half g_k[(size_t)NWIN * NH_ * N_ * HD];
__device__ __half g_v[(size_t)NWIN * NH_ * N_ * HD];
__device__ __half g_rpbh[(size_t)NH_ * N_ * RLD];  // half, padded rows
__device__ __half g_ao[(size_t)M_ * C];          // attention output (proj input)

// ---------------------------------------------------------------------------
// prep kernels
// ---------------------------------------------------------------------------
__global__ void prep_w_kernel(const float* __restrict__ qkvw,
                              const float* __restrict__ projw,
                              const float* __restrict__ qb,
                              const float* __restrict__ vb) {
  int g = blockIdx.x * 256 + threadIdx.x;
  if (g < 2304 * 768) g_wqkv[g] = __float2half(qkvw[g]);
  if (g < 768 * 768)  g_wproj[g] = __float2half(projw[g]);
  if (g < 2304) g_bqkv[g] = (g < 768) ? qb[g] : ((g < 1536) ? 0.0f : vb[g - 1536]);
}

__global__ void rpb_kernel(const float* __restrict__ table) {
  int g = blockIdx.x * 256 + threadIdx.x;
  if (g >= N_ * RLD) return;
  int a = g / RLD, b = g - a * RLD;
  if (b >= N_) {
#pragma unroll
    for (int hh = 0; hh < NH_; hh++)
      g_rpbh[(size_t)hh * N_ * RLD + g] = __float2half(0.0f);
    return;
  }
  int i1 = a / WS_, j1 = a - i1 * WS_;
  int i2 = b / WS_, j2 = b - i2 * WS_;
  int idx = (i1 - i2 + WS_ - 1) * (2 * WS_ - 1) + (j1 - j2 + WS_ - 1);
#pragma unroll
  for (int hh = 0; hh < NH_; hh++)
    g_rpbh[(size_t)hh * N_ * RLD + g] = __float2half(table[idx * NH_ + hh]);
}

// x [B, H*W, C] fp32 -> g_xh [win*196, C] fp16 (window partition gather fused)
__global__ void convx_kernel(const float* __restrict__ x) {
  int g = blockIdx.x * 256 + threadIdx.x;
  int m = g / 96, kk = g - m * 96;
  int w = m / N_, n = m - w * N_;
  int b = w >> 4, wr = w & 15, wh = wr >> 2, ww = wr & 3;
  int ii = n / WS_, jj = n - ii * WS_;
  size_t xr = (size_t)b * (HH * WWp) + (size_t)(wh * WS_ + ii) * WWp + (ww * WS_ + jj);
  const float4* src = (const float4*)(x + xr * C + kk * 8);
  float4 v0 = src[0], v1 = src[1];
  union { int4 i4; __half2 h2v[4]; } o;
  o.h2v[0] = __floats2half2_rn(v0.x, v0.y);
  o.h2v[1] = __floats2half2_rn(v0.z, v0.w);
  o.h2v[2] = __floats2half2_rn(v1.x, v1.y);
  o.h2v[3] = __floats2half2_rn(v1.z, v1.w);
  *(int4*)(g_xh + (size_t)m * C + kk * 8) = o.i4;
}

// ---------------------------------------------------------------------------
// WMMA GEMM v4: out[m, c] = sum_k A[m,k] * B[c,k] + bias[c]
// CTA 256 thr, tile 128x128, warp tile 32x64 (2x4 wmma frags), k-step 32,
// 4-stage cp.async pipeline with a SINGLE barrier per k-iter (S=4 rotation
// makes the trailing barrier redundant), 2 CTAs/SM resident.
// MODE 0: QKV (A=g_xh, B=g_wqkv -> g_q/g_k/g_v, q scaled 0.125)
// MODE 1: proj (A=g_ao, B=g_wproj -> d_out image layout)
// ---------------------------------------------------------------------------
template <int MODE>
__global__ __launch_bounds__(256, 2) void gemm4_kernel(const float* __restrict__ bias_in,
                                                       float* __restrict__ out_f) {
  constexpr int BM = 128, BN = 128, BK = 32, S = 4;
  constexpr int LDA = 40, LDB = 40, LDE = 132;
  constexpr int NKT = KQ / BK;                       // 24
  constexpr int ABYTES = BM * LDA * 2;               // 10240
  constexpr int BBYTES = BN * LDB * 2;               // 10240
  constexpr int STG = ABYTES + BBYTES;               // 20480

  extern __shared__ __align__(16) char dsm[];
  float* ep = (float*)dsm;                           // epilogue reuse

  const __half* __restrict__ A  = (MODE == 0) ? g_xh : g_ao;
  const __half* __restrict__ Bw = (MODE == 0) ? g_wqkv : g_wproj;
  const int n0 = blockIdx.x * BN;
  const int m0 = blockIdx.y * BM;
  const int tid = threadIdx.x;
  const int warp = tid >> 5;
  const int wm = warp >> 1, wn = warp & 1;           // 4 x 2 warp grid

  wmma::fragment<wmma::accumulator, 16, 16, 16, float> acc[2][4];
#pragma unroll
  for (int i = 0; i < 2; i++)
#pragma unroll
    for (int j = 0; j < 4; j++) wmma::fill_fragment(acc[i][j], 0.0f);

  auto load_stage = [&](int kt) {
    const int slot = kt % S;
    char* abase = dsm + slot * STG;
    char* bbase = abase + ABYTES;
    const char* ag = (const char*)(A + (size_t)m0 * KQ + kt * BK);
    const char* bg = (const char*)(Bw + (size_t)n0 * KQ + kt * BK);
#pragma unroll
    for (int i = 0; i < 2; i++) {                    // A: 128 rows x 64B
      int q = tid + i * 256; int r = q >> 2, co = q & 3;
      asm volatile("{ .reg .u64 t; cvta.to.shared.u64 t, %0; .reg .u32 s; cvt.u32.u64 s, t;"
                   " cp.async.cg.shared.global [s], [%1], 16; }"
                   :: "l"(abase + r * (LDA * 2) + co * 16),
                      "l"(ag + (size_t)r * (KQ * 2) + co * 16) : "memory");
    }
#pragma unroll
    for (int i = 0; i < 2; i++) {                    // B: 128 rows x 64B
      int q = tid + i * 256; int r = q >> 2, co = q & 3;
      asm volatile("{ .reg .u64 t; cvta.to.shared.u64 t, %0; .reg .u32 s; cvt.u32.u64 s, t;"
                   " cp.async.cg.shared.global [s], [%1], 16; }"
                   :: "l"(bbase + r * (LDB * 2) + co * 16),
                      "l"(bg + (size_t)r * (KQ * 2) + co * 16) : "memory");
    }
    asm volatile("cp.async.commit_group;" ::: "memory");
  };

  load_stage(0);
  load_stage(1);
  load_stage(2);

  for (int kt = 0; kt < NKT; kt++) {
    if (kt < NKT - 2) asm volatile("cp.async.wait_group 2;" ::: "memory");
    else              asm volatile("cp.async.wait_group 0;" ::: "memory");
    __syncthreads();                                 // the only barrier per iter
    if (kt + 3 < NKT) load_stage(kt + 3);

    const int slot = kt % S;
    const __half* sA = (const __half*)(dsm + slot * STG);
    const __half* sB = (const __half*)(dsm + slot * STG + ABYTES);
#pragma unroll
    for (int ks = 0; ks < 2; ks++) {
      wmma::fragment<wmma::matrix_a, 16, 16, 16, __half, wmma::row_major> af[2];
      wmma::fragment<wmma::matrix_b, 16, 16, 16, __half, wmma::col_major> bf[4];
#pragma unroll
      for (int i = 0; i < 2; i++)
        wmma::load_matrix_sync(af[i], &sA[(wm * 32 + i * 16) * LDA + ks * 16], LDA);
#pragma unroll
      for (int j = 0; j < 4; j++)
        wmma::load_matrix_sync(bf[j], &sB[(wn * 64 + j * 16) * LDB + ks * 16], LDB);
#pragma unroll
      for (int i = 0; i < 2; i++)
#pragma unroll
        for (int j = 0; j < 4; j++)
          wmma::mma_sync(acc[i][j], af[i], bf[j], acc[i][j]);
    }
  }

  // epilogue: all frags -> smem -> fused bias + vectorized scatter
  __syncthreads();
#pragma unroll
  for (int i = 0; i < 2; i++)
#pragma unroll
    for (int j = 0; j < 4; j++)
      wmma::store_matrix_sync(&ep[(wm * 32 + i * 16) * LDE + wn * 64 + j * 16],
                              acc[i][j], LDE, wmma::mem_row_major);
  __syncthreads();
#pragma unroll 4
  for (int it = 0; it < 32; it++) {                  // 128x128 / 2 = 8192 pairs
    int idx = it * 256 + tid;
    int r = idx >> 6, ccp = idx & 63;
    int cc = ccp * 2;
    int m = m0 + r;
    int c = n0 + cc;
    float v0 = ep[r * LDE + cc];
    float v1 = ep[r * LDE + cc + 1];
    int w = m / N_, n = m - w * N_;
    if (MODE == 0) {
      v0 += g_bqkv[c];
      v1 += g_bqkv[c + 1];
      int sec = c / 768, cu = c - sec * 768;
      int h = cu >> 6, d = cu & 63;                  // pair stays within one head
      __half* dst = ((sec == 0) ? g_q : (sec == 1) ? g_k : g_v) +
                    ((size_t)(w * NH_ + h) * N_ + n) * HD + d;
      float sc = (sec == 0) ? 0.125f : 1.0f;
      *(__half2*)dst = __floats2half2_rn(v0 * sc, v1 * sc);
    } else {
      v0 += bias_in[c];
      v1 += bias_in[c + 1];
      int b = w >> 4, wr = w & 15, wh = wr >> 2, ww = wr & 3;
      int ii = n / WS_, jj = n - ii * WS_;
      size_t xr = (size_t)b * (HH * WWp) + (size_t)(wh * WS_ + ii) * WWp + (ww * WS_ + jj);
      *(float2*)(out_f + xr * C + c) = make_float2(v0, v1);
    }
  }
}

// ---------------------------------------------------------------------------
// attention v2: one block per (window, head, 64-row q chunk). The block's
// 64x200 rpb slice is staged ONCE into smem (coalesced int4) instead of
// 2048 scattered per-element LDGs per key-tile. Dynamic smem, 3 CTAs/SM.
// ---------------------------------------------------------------------------
__global__ __launch_bounds__(128) void attn_kernel() {
  constexpr int LQ = 72, LK = 72, LV = 80, LS = 36, LP = 40, LO = 84;
  constexpr int KT = 32, NT = 7;
  constexpr int QBYTES = 64 * LQ * 2;      // 9216
  constexpr int UBYTES = 24064;            // max(K+V+S+P, O) region

  extern __shared__ __align__(16) char asmem[];
  __half* Qs = (__half*)asmem;
  char*   ub = asmem + QBYTES;
  __half* Ks = (__half*)ub;                          // 32*72*2 = 4608
  __half* Vs = (__half*)(ub + 4608);                 // 32*80*2 = 5120
  float*  Ss = (float*)(ub + 9728);                  // 64*36*4 = 9216
  __half* Ps = (__half*)(ub + 18944);                // 64*40*2 = 5120 -> 24064
  float*  Os = (float*)ub;                           // reuse, 64*84*4 = 21504
  __half* Rs = (__half*)(asmem + QBYTES + UBYTES);   // 64*200*2 = 25600

  const int qc = blockIdx.x, h = blockIdx.y, w = blockIdx.z;
  const int tid = threadIdx.x, warp = tid >> 5;
  const size_t base = ((size_t)w * NH_ + h) * N_ * HD;
  const __half* Qg = g_q + base;
  const __half* Kg = g_k + base;
  const __half* Vg = g_v + base;

  // load Q chunk (64 rows, zero-pad past 196)
#pragma unroll
  for (int i = 0; i < 4; i++) {
    int p = tid + i * 128;
    int r = p >> 3, ko = (p & 7) << 3;
    int n = qc * 64 + r;
    int4 val = (n < N_) ? *(const int4*)(Qg + (size_t)n * HD + ko) : make_int4(0, 0, 0, 0);
    *(int4*)&Qs[r * LQ + ko] = val;
  }

  // stage rpb slice: 64 rows x 200 halfs = 1600 int4, coalesced
  {
    const int4* rsrc = (const int4*)(g_rpbh + (size_t)h * N_ * RLD);
    int4* rdst = (int4*)Rs;
#pragma unroll
    for (int i = 0; i < 13; i++) {
      int idx = i * 128 + tid;
      if (idx < 1600) {
        int r = idx / 25, cquad = idx - r * 25;
        int n = qc * 64 + r;
        rdst[r * 25 + cquad] = (n < N_) ? rsrc[(size_t)n * 25 + cquad]
                                        : make_int4(0, 0, 0, 0);
      }
    }
  }

  wmma::fragment<wmma::accumulator, 16, 16, 16, float> oacc[5];
#pragma unroll
  for (int c = 0; c < 5; c++) wmma::fill_fragment(oacc[c], 0.0f);
  __syncthreads();

  for (int t = 0; t < NT; t++) {
#pragma unroll
    for (int i = 0; i < 2; i++) {
      int p = tid + i * 128;
      int r = p >> 3, ko = (p & 7) << 3;
      int jg = t * KT + r;
      int4 kv, vv;
      if (jg < N_) {
        kv = *(const int4*)(Kg + (size_t)jg * HD + ko);
        vv = *(const int4*)(Vg + (size_t)jg * HD + ko);
      } else { kv = make_int4(0, 0, 0, 0); vv = kv; }
      *(int4*)&Ks[r * LK + ko] = kv;
      *(int4*)&Vs[r * LV + ko] = vv;
    }
    if (tid < KT) {
      int jg = t * KT + tid;
      __half one = __float2half(jg < N_ ? 1.0f : 0.0f);
#pragma unroll
      for (int co = 0; co < 16; co++)
        Vs[tid * LV + 64 + co] = (co == 0) ? one : __float2half(0.0f);
    }
    __syncthreads();

    // S = Q K^T
    {
      wmma::fragment<wmma::matrix_a, 16, 16, 16, __half, wmma::row_major> qa[4];
#pragma unroll
      for (int kk = 0; kk < 4; kk++)
        wmma::load_matrix_sync(qa[kk], &Qs[(warp * 16) * LQ + kk * 16], LQ);
#pragma unroll
      for (int j = 0; j < 2; j++) {
        wmma::fragment<wmma::accumulator, 16, 16, 16, float> sacc;
        wmma::fill_fragment(sacc, 0.0f);
#pragma unroll
        for (int kk = 0; kk < 4; kk++) {
          wmma::fragment<wmma::matrix_b, 16, 16, 16, __half, wmma::col_major> kb;
          wmma::load_matrix_sync(kb, &Ks[(j * 16) * LK + kk * 16], LK);
          wmma::mma_sync(sacc, qa[kk], kb, sacc);
        }
        wmma::store_matrix_sync(&Ss[(warp * 16) * LS + j * 16], sacc, LS, wmma::mem_row_major);
      }
    }
    __syncthreads();

    // P = exp(S + rpb), zero for padded rows/cols (rpb read from smem)
#pragma unroll
    for (int i = 0; i < 16; i++) {
      int idx = i * 128 + tid;
      int r = idx >> 5, j = idx & 31;
      int n = qc * 64 + r, jg = t * KT + j;
      float val = 0.0f;
      if (n < N_ && jg < N_) {
        float s = Ss[r * LS + j] + __half2float(Rs[r * RLD + t * KT + j]);
        val = __expf(s);
      }
      Ps[r * LP + j] = __float2half(val);
    }
    __syncthreads();

    // O += P V (col frag 4 accumulates the row-sum normalizer)
    {
      wmma::fragment<wmma::matrix_a, 16, 16, 16, __half, wmma::row_major> pa[2];
#pragma unroll
      for (int kk = 0; kk < 2; kk++)
        wmma::load_matrix_sync(pa[kk], &Ps[(warp * 16) * LP + kk * 16], LP);
#pragma unroll
      for (int c = 0; c < 5; c++) {
#pragma unroll
        for (int kk = 0; kk < 2; kk++) {
          wmma::fragment<wmma::matrix_b, 16, 16, 16, __half, wmma::row_major> vb;
          wmma::load_matrix_sync(vb, &Vs[(kk * 16) * LV + c * 16], LV);
          wmma::mma_sync(oacc[c], pa[kk], vb, oacc[c]);
        }
      }
    }
    __syncthreads();
  }

  // normalize + write
#pragma unroll
  for (int c = 0; c < 5; c++)
    wmma::store_matrix_sync(&Os[(warp * 16) * LO + c * 16], oacc[c], LO, wmma::mem_row_major);
  __syncthreads();
#pragma unroll
  for (int i = 0; i < 32; i++) {
    int idx = i * 128 + tid;
    int r = idx >> 6, d = idx & 63;
    int n = qc * 64 + r;
    if (n < N_) {
      float l = Os[r * LO + 64];
      float o = Os[r * LO + d] / l;
      g_ao[((size_t)w * N_ + n) * C + h * HD + d] = __float2half(o);
    }
  }
}

// ---------------------------------------------------------------------------
extern "C" void kernel_launch(void* const* d_in, const int* in_sizes, int n_in,
                              void* d_out, int out_size) {
  const float* x     = (const float*)d_in[0];
  const float* qkvw  = (const float*)d_in[1];
  const float* qb    = (const float*)d_in[2];
  const float* vb    = (const float*)d_in[3];
  const float* table = (const float*)d_in[4];
  const float* projw = (const float*)d_in[5];
  const float* projb = (const float*)d_in[6];
  float* out = (float*)d_out;
  (void)in_sizes; (void)n_in; (void)out_size;

  const int DSMEM_G = 4 * 20480;                     // 81920 (> epilogue 67584)
  const int DSMEM_A = 9216 + 24064 + 25600;          // 58880
  cudaFuncSetAttribute(gemm4_kernel<0>, cudaFuncAttributeMaxDynamicSharedMemorySize, DSMEM_G);
  cudaFuncSetAttribute(gemm4_kernel<1>, cudaFuncAttributeMaxDynamicSharedMemorySize, DSMEM_G);
  cudaFuncSetAttribute(attn_kernel, cudaFuncAttributeMaxDynamicSharedMemorySize, DSMEM_A);

  prep_w_kernel<<<(2304 * 768) / 256, 256>>>(qkvw, projw, qb, vb);
  rpb_kernel<<<(N_ * RLD + 255) / 256, 256>>>(table);
  convx_kernel<<<(M_ * 96) / 256, 256>>>(x);
  gemm4_kernel<0><<<dim3(2304 / 128, M_ / 128), 256, DSMEM_G>>>(nullptr, nullptr);
  attn_kernel<<<dim3(4, NH_, NWIN), 128, DSMEM_A>>>();
  gemm4_kernel<1><<<dim3(768 / 128, M_ / 128), 256, DSMEM_G>>>(projb, out);
}

// round 6
// speedup vs baseline: 1.3372x; 1.0643x over previous
#include <cuda_runtime.h>
#include <cuda_fp16.h>
#include <mma.h>
#include <cstdint>

using namespace nvcuda;

// Problem constants (static shapes)
constexpr int HH   = 56;
constexpr int WWp  = 56;
constexpr int C    = 768;
constexpr int NH_  = 12;
constexpr int HD   = 64;
constexpr int WS_  = 14;
constexpr int N_   = 196;        // tokens per window
constexpr int NWIN = 256;        // 16 batch * 16 windows
constexpr int M_   = NWIN * N_;  // 50176 rows
constexpr int KQ   = 768;
constexpr int RLD  = 224;        // padded rpb row stride (halfs) = 7 tiles x 32

// -------- device scratch (allocation-free rule: __device__ globals) --------
__device__ __half g_xh[(size_t)M_ * C];          // window-ordered fp16 x
__device__ __half g_wqkv[2304 * 768];
__device__ __half g_wproj[768 * 768];
__device__ float  g_bqkv[2304];
__device__ __half g_q[(size_t)NWIN * NH_ * N_ * HD];
__device__ __half g_k[(size_t)NWIN * NH_ * N_ * HD];
__device__ __half g_v[(size_t)NWIN * NH_ * N_ * HD];
__device__ __half g_rpbh[(size_t)NH_ * N_ * RLD];  // half, padded rows
__device__ __half g_ao[(size_t)M_ * C];          // attention output (proj input)

// ---------------------------------------------------------------------------
// prep kernels
// ---------------------------------------------------------------------------
__global__ void prep_w_kernel(const float* __restrict__ qkvw,
                              const float* __restrict__ projw,
                              const float* __restrict__ qb,
                              const float* __restrict__ vb) {
  int g = blockIdx.x * 256 + threadIdx.x;
  if (g < 2304 * 768) g_wqkv[g] = __float2half(qkvw[g]);
  if (g < 768 * 768)  g_wproj[g] = __float2half(projw[g]);
  if (g < 2304) g_bqkv[g] = (g < 768) ? qb[g] : ((g < 1536) ? 0.0f : vb[g - 1536]);
}

__global__ void rpb_kernel(const float* __restrict__ table) {
  int g = blockIdx.x * 256 + threadIdx.x;
  if (g >= N_ * RLD) return;
  int a = g / RLD, b = g - a * RLD;
  if (b >= N_) {
#pragma unroll
    for (int hh = 0; hh < NH_; hh++)
      g_rpbh[(size_t)hh * N_ * RLD + g] = __float2half(0.0f);
    return;
  }
  int i1 = a / WS_, j1 = a - i1 * WS_;
  int i2 = b / WS_, j2 = b - i2 * WS_;
  int idx = (i1 - i2 + WS_ - 1) * (2 * WS_ - 1) + (j1 - j2 + WS_ - 1);
#pragma unroll
  for (int hh = 0; hh < NH_; hh++)
    g_rpbh[(size_t)hh * N_ * RLD + g] = __float2half(table[idx * NH_ + hh]);
}

// x [B, H*W, C] fp32 -> g_xh [win*196, C] fp16 (window partition gather fused)
__global__ void convx_kernel(const float* __restrict__ x) {
  int g = blockIdx.x * 256 + threadIdx.x;
  int m = g / 96, kk = g - m * 96;
  int w = m / N_, n = m - w * N_;
  int b = w >> 4, wr = w & 15, wh = wr >> 2, ww = wr & 3;
  int ii = n / WS_, jj = n - ii * WS_;
  size_t xr = (size_t)b * (HH * WWp) + (size_t)(wh * WS_ + ii) * WWp + (ww * WS_ + jj);
  const float4* src = (const float4*)(x + xr * C + kk * 8);
  float4 v0 = src[0], v1 = src[1];
  union { int4 i4; __half2 h2v[4]; } o;
  o.h2v[0] = __floats2half2_rn(v0.x, v0.y);
  o.h2v[1] = __floats2half2_rn(v0.z, v0.w);
  o.h2v[2] = __floats2half2_rn(v1.x, v1.y);
  o.h2v[3] = __floats2half2_rn(v1.z, v1.w);
  *(int4*)(g_xh + (size_t)m * C + kk * 8) = o.i4;
}

// ---------------------------------------------------------------------------
// WMMA GEMM v5: out[m, c] = sum_k A[m,k] * B[c,k] + bias[c]
// CTA 128 thr (4 warps, 2x2), tile 128x128, warp tile 64x64 (4x4 frags) ->
// 0.031 B/FLOP smem traffic (crossbar cap ~75% tensor), 2 CTAs/SM resident,
// 3-stage cp.async with single barrier per k-iter.
// MODE 0: QKV (A=g_xh, B=g_wqkv -> g_q/g_k/g_v, q scaled 0.125)
// MODE 1: proj (A=g_ao, B=g_wproj -> d_out image layout)
// ---------------------------------------------------------------------------
template <int MODE>
__global__ __launch_bounds__(128, 2) void gemm5_kernel(const float* __restrict__ bias_in,
                                                       float* __restrict__ out_f) {
  constexpr int BM = 128, BN = 128, BK = 32, S = 3;
  constexpr int LDA = 40, LDB = 40, LDE = 68;
  constexpr int NKT = KQ / BK;                       // 24
  constexpr int ABYTES = BM * LDA * 2;               // 10240
  constexpr int BBYTES = BN * LDB * 2;               // 10240
  constexpr int STG = ABYTES + BBYTES;               // 20480

  extern __shared__ __align__(16) char dsm[];
  float* ep = (float*)dsm;                           // epilogue reuse (128x68 f32)

  const __half* __restrict__ A  = (MODE == 0) ? g_xh : g_ao;
  const __half* __restrict__ Bw = (MODE == 0) ? g_wqkv : g_wproj;
  const int n0 = blockIdx.x * BN;
  const int m0 = blockIdx.y * BM;
  const int tid = threadIdx.x;
  const int warp = tid >> 5;
  const int wm = warp >> 1, wn = warp & 1;           // 2 x 2 warp grid

  wmma::fragment<wmma::accumulator, 16, 16, 16, float> acc[4][4];
#pragma unroll
  for (int i = 0; i < 4; i++)
#pragma unroll
    for (int j = 0; j < 4; j++) wmma::fill_fragment(acc[i][j], 0.0f);

  auto load_stage = [&](int kt) {
    const int slot = kt % S;
    char* abase = dsm + slot * STG;
    char* bbase = abase + ABYTES;
    const char* ag = (const char*)(A + (size_t)m0 * KQ + kt * BK);
    const char* bg = (const char*)(Bw + (size_t)n0 * KQ + kt * BK);
#pragma unroll
    for (int i = 0; i < 4; i++) {                    // A: 128 rows x 64B
      int q = tid + i * 128; int r = q >> 2, co = q & 3;
      asm volatile("{ .reg .u64 t; cvta.to.shared.u64 t, %0; .reg .u32 s; cvt.u32.u64 s, t;"
                   " cp.async.cg.shared.global [s], [%1], 16; }"
                   :: "l"(abase + r * (LDA * 2) + co * 16),
                      "l"(ag + (size_t)r * (KQ * 2) + co * 16) : "memory");
    }
#pragma unroll
    for (int i = 0; i < 4; i++) {                    // B: 128 rows x 64B
      int q = tid + i * 128; int r = q >> 2, co = q & 3;
      asm volatile("{ .reg .u64 t; cvta.to.shared.u64 t, %0; .reg .u32 s; cvt.u32.u64 s, t;"
                   " cp.async.cg.shared.global [s], [%1], 16; }"
                   :: "l"(bbase + r * (LDB * 2) + co * 16),
                      "l"(bg + (size_t)r * (KQ * 2) + co * 16) : "memory");
    }
    asm volatile("cp.async.commit_group;" ::: "memory");
  };

  load_stage(0);
  load_stage(1);

  for (int kt = 0; kt < NKT; kt++) {
    if (kt < NKT - 1) asm volatile("cp.async.wait_group 1;" ::: "memory");
    else              asm volatile("cp.async.wait_group 0;" ::: "memory");
    __syncthreads();                                 // the only barrier per iter
    if (kt + 2 < NKT) load_stage(kt + 2);

    const int slot = kt % S;
    const __half* sA = (const __half*)(dsm + slot * STG);
    const __half* sB = (const __half*)(dsm + slot * STG + ABYTES);
#pragma unroll
    for (int ks = 0; ks < 2; ks++) {
      wmma::fragment<wmma::matrix_a, 16, 16, 16, __half, wmma::row_major> af[4];
      wmma::fragment<wmma::matrix_b, 16, 16, 16, __half, wmma::col_major> bf[4];
#pragma unroll
      for (int i = 0; i < 4; i++)
        wmma::load_matrix_sync(af[i], &sA[(wm * 64 + i * 16) * LDA + ks * 16], LDA);
#pragma unroll
      for (int j = 0; j < 4; j++)
        wmma::load_matrix_sync(bf[j], &sB[(wn * 64 + j * 16) * LDB + ks * 16], LDB);
#pragma unroll
      for (int i = 0; i < 4; i++)
#pragma unroll
        for (int j = 0; j < 4; j++)
          wmma::mma_sync(acc[i][j], af[i], bf[j], acc[i][j]);
    }
  }

  // epilogue: 2 phases of 64 cols through smem, fused bias + vectorized scatter
#pragma unroll 1
  for (int p = 0; p < 2; p++) {
    __syncthreads();
    if (wn == p) {
#pragma unroll
      for (int i = 0; i < 4; i++)
#pragma unroll
        for (int j = 0; j < 4; j++)
          wmma::store_matrix_sync(&ep[(wm * 64 + i * 16) * LDE + j * 16],
                                  acc[i][j], LDE, wmma::mem_row_major);
    }
    __syncthreads();
#pragma unroll 4
    for (int it = 0; it < 32; it++) {                // 128 rows x 32 pairs
      int idx = it * 128 + tid;
      int r = idx >> 5, ccp = idx & 31;
      int cc = ccp * 2;
      int m = m0 + r;
      int c = n0 + p * 64 + cc;
      float v0 = ep[r * LDE + cc];
      float v1 = ep[r * LDE + cc + 1];
      int w = m / N_, n = m - w * N_;
      if (MODE == 0) {
        v0 += g_bqkv[c];
        v1 += g_bqkv[c + 1];
        int sec = c / 768, cu = c - sec * 768;
        int h = cu >> 6, d = cu & 63;                // pair stays within one head
        __half* dst = ((sec == 0) ? g_q : (sec == 1) ? g_k : g_v) +
                      ((size_t)(w * NH_ + h) * N_ + n) * HD + d;
        float sc = (sec == 0) ? 0.125f : 1.0f;
        *(__half2*)dst = __floats2half2_rn(v0 * sc, v1 * sc);
      } else {
        v0 += bias_in[c];
        v1 += bias_in[c + 1];
        int b = w >> 4, wr = w & 15, wh = wr >> 2, ww = wr & 3;
        int ii = n / WS_, jj = n - ii * WS_;
        size_t xr = (size_t)b * (HH * WWp) + (size_t)(wh * WS_ + ii) * WWp + (ww * WS_ + jj);
        *(float2*)(out_f + xr * C + c) = make_float2(v0, v1);
      }
    }
  }
}

// ---------------------------------------------------------------------------
// attention v3: one block per (window, head, 64-row q chunk). rpb staged
// PER KEY-TILE (4KB buffer, coalesced) inside the existing barrier structure.
// smem 37.4KB -> 6 CTAs/SM. Normalizer via ones-column appended to V.
// ---------------------------------------------------------------------------
__global__ __launch_bounds__(128) void attn_kernel() {
  constexpr int LQ = 72, LK = 72, LV = 80, LS = 36, LP = 40, LO = 84;
  constexpr int KT = 32, NT = 7;
  constexpr int QBYTES = 64 * LQ * 2;                // 9216

  extern __shared__ __align__(16) char asmem[];
  __half* Qs = (__half*)asmem;
  char*   ub = asmem + QBYTES;
  __half* Ks = (__half*)ub;                          // 4608
  __half* Vs = (__half*)(ub + 4608);                 // 5120
  float*  Ss = (float*)(ub + 9728);                  // 9216
  __half* Ps = (__half*)(ub + 18944);                // 5120
  __half* Rt = (__half*)(ub + 24064);                // 64*32*2 = 4096 -> 28160
  float*  Os = (float*)ub;                           // reuse (21504)

  const int qc = blockIdx.x, h = blockIdx.y, w = blockIdx.z;
  const int tid = threadIdx.x, warp = tid >> 5;
  const size_t base = ((size_t)w * NH_ + h) * N_ * HD;
  const __half* Qg = g_q + base;
  const __half* Kg = g_k + base;
  const __half* Vg = g_v + base;
  const __half* Rg = g_rpbh + (size_t)h * N_ * RLD;

  // load Q chunk (64 rows, zero-pad past 196)
#pragma unroll
  for (int i = 0; i < 4; i++) {
    int p = tid + i * 128;
    int r = p >> 3, ko = (p & 7) << 3;
    int n = qc * 64 + r;
    int4 val = (n < N_) ? *(const int4*)(Qg + (size_t)n * HD + ko) : make_int4(0, 0, 0, 0);
    *(int4*)&Qs[r * LQ + ko] = val;
  }

  wmma::fragment<wmma::accumulator, 16, 16, 16, float> oacc[5];
#pragma unroll
  for (int c = 0; c < 5; c++) wmma::fill_fragment(oacc[c], 0.0f);
  __syncthreads();

  for (int t = 0; t < NT; t++) {
    // K,V tiles (32 rows x 64)
#pragma unroll
    for (int i = 0; i < 2; i++) {
      int p = tid + i * 128;
      int r = p >> 3, ko = (p & 7) << 3;
      int jg = t * KT + r;
      int4 kv, vv;
      if (jg < N_) {
        kv = *(const int4*)(Kg + (size_t)jg * HD + ko);
        vv = *(const int4*)(Vg + (size_t)jg * HD + ko);
      } else { kv = make_int4(0, 0, 0, 0); vv = kv; }
      *(int4*)&Ks[r * LK + ko] = kv;
      *(int4*)&Vs[r * LV + ko] = vv;
    }
    // rpb tile: 64 rows x 32 halfs = 256 int4, coalesced
#pragma unroll
    for (int i = 0; i < 2; i++) {
      int p = tid + i * 128;
      int r = p >> 2, q4 = p & 3;
      int n = qc * 64 + r;
      int4 rv = (n < N_) ? *(const int4*)(Rg + (size_t)n * RLD + t * KT + q4 * 8)
                         : make_int4(0, 0, 0, 0);
      *(int4*)&Rt[r * KT + q4 * 8] = rv;
    }
    if (tid < KT) {
      int jg = t * KT + tid;
      __half one = __float2half(jg < N_ ? 1.0f : 0.0f);
#pragma unroll
      for (int co = 0; co < 16; co++)
        Vs[tid * LV + 64 + co] = (co == 0) ? one : __float2half(0.0f);
    }
    __syncthreads();

    // S = Q K^T
    {
      wmma::fragment<wmma::matrix_a, 16, 16, 16, __half, wmma::row_major> qa[4];
#pragma unroll
      for (int kk = 0; kk < 4; kk++)
        wmma::load_matrix_sync(qa[kk], &Qs[(warp * 16) * LQ + kk * 16], LQ);
#pragma unroll
      for (int j = 0; j < 2; j++) {
        wmma::fragment<wmma::accumulator, 16, 16, 16, float> sacc;
        wmma::fill_fragment(sacc, 0.0f);
#pragma unroll
        for (int kk = 0; kk < 4; kk++) {
          wmma::fragment<wmma::matrix_b, 16, 16, 16, __half, wmma::col_major> kb;
          wmma::load_matrix_sync(kb, &Ks[(j * 16) * LK + kk * 16], LK);
          wmma::mma_sync(sacc, qa[kk], kb, sacc);
        }
        wmma::store_matrix_sync(&Ss[(warp * 16) * LS + j * 16], sacc, LS, wmma::mem_row_major);
      }
    }
    __syncthreads();

    // P = exp(S + rpb) from smem, zero for padded rows/cols
#pragma unroll
    for (int i = 0; i < 16; i++) {
      int idx = i * 128 + tid;
      int r = idx >> 5, j = idx & 31;
      int n = qc * 64 + r, jg = t * KT + j;
      float val = 0.0f;
      if (n < N_ && jg < N_) {
        float s = Ss[r * LS + j] + __half2float(Rt[r * KT + j]);
        val = __expf(s);
      }
      Ps[r * LP + j] = __float2half(val);
    }
    __syncthreads();

    // O += P V (col frag 4 accumulates the row-sum normalizer)
    {
      wmma::fragment<wmma::matrix_a, 16, 16, 16, __half, wmma::row_major> pa[2];
#pragma unroll
      for (int kk = 0; kk < 2; kk++)
        wmma::load_matrix_sync(pa[kk], &Ps[(warp * 16) * LP + kk * 16], LP);
#pragma unroll
      for (int c = 0; c < 5; c++) {
#pragma unroll
        for (int kk = 0; kk < 2; kk++) {
          wmma::fragment<wmma::matrix_b, 16, 16, 16, __half, wmma::row_major> vb;
          wmma::load_matrix_sync(vb, &Vs[(kk * 16) * LV + c * 16], LV);
          wmma::mma_sync(oacc[c], pa[kk], vb, oacc[c]);
        }
      }
    }
    __syncthreads();
  }

  // normalize + write
#pragma unroll
  for (int c = 0; c < 5; c++)
    wmma::store_matrix_sync(&Os[(warp * 16) * LO + c * 16], oacc[c], LO, wmma::mem_row_major);
  __syncthreads();
#pragma unroll
  for (int i = 0; i < 32; i++) {
    int idx = i * 128 + tid;
    int r = idx >> 6, d = idx & 63;
    int n = qc * 64 + r;
    if (n < N_) {
      float l = Os[r * LO + 64];
      float o = Os[r * LO + d] / l;
      g_ao[((size_t)w * N_ + n) * C + h * HD + d] = __float2half(o);
    }
  }
}

// ---------------------------------------------------------------------------
extern "C" void kernel_launch(void* const* d_in, const int* in_sizes, int n_in,
                              void* d_out, int out_size) {
  const float* x     = (const float*)d_in[0];
  const float* qkvw  = (const float*)d_in[1];
  const float* qb    = (const float*)d_in[2];
  const float* vb    = (const float*)d_in[3];
  const float* table = (const float*)d_in[4];
  const float* projw = (const float*)d_in[5];
  const float* projb = (const float*)d_in[6];
  float* out = (float*)d_out;
  (void)in_sizes; (void)n_in; (void)out_size;

  const int DSMEM_G = 3 * 20480;                     // 61440 (> epilogue 34816)
  const int DSMEM_A = 9216 + 28160;                  // 37376
  cudaFuncSetAttribute(gemm5_kernel<0>, cudaFuncAttributeMaxDynamicSharedMemorySize, DSMEM_G);
  cudaFuncSetAttribute(gemm5_kernel<1>, cudaFuncAttributeMaxDynamicSharedMemorySize, DSMEM_G);
  cudaFuncSetAttribute(attn_kernel, cudaFuncAttributeMaxDynamicSharedMemorySize, DSMEM_A);

  prep_w_kernel<<<(2304 * 768) / 256, 256>>>(qkvw, projw, qb, vb);
  rpb_kernel<<<(N_ * RLD + 255) / 256, 256>>>(table);
  convx_kernel<<<(M_ * 96) / 256, 256>>>(x);
  gemm5_kernel<0><<<dim3(2304 / 128, M_ / 128), 128, DSMEM_G>>>(nullptr, nullptr);
  attn_kernel<<<dim3(4, NH_, NWIN), 128, DSMEM_A>>>();
  gemm5_kernel<1><<<dim3(768 / 128, M_ / 128), 128, DSMEM_G>>>(projb, out);
}

// round 7
// speedup vs baseline: 1.4594x; 1.0914x over previous
#include <cuda_runtime.h>
#include <cuda_fp16.h>
#include <mma.h>
#include <cstdint>

using namespace nvcuda;

// Problem constants (static shapes)
constexpr int HH   = 56;
constexpr int WWp  = 56;
constexpr int C    = 768;
constexpr int NH_  = 12;
constexpr int HD   = 64;
constexpr int WS_  = 14;
constexpr int N_   = 196;        // tokens per window
constexpr int NWIN = 256;        // 16 batch * 16 windows
constexpr int M_   = NWIN * N_;  // 50176 rows
constexpr int KQ   = 768;
constexpr int RLD  = 224;        // padded rpb row stride (halfs) = 7 tiles x 32

// -------- device scratch (allocation-free rule: __device__ globals) --------
__device__ __half g_xh[(size_t)M_ * C];          // window-ordered fp16 x
__device__ __half g_wqkv[2304 * 768];
__device__ __half g_wproj[768 * 768];
__device__ float  g_bqkv[2304];
__device__ __half g_q[(size_t)NWIN * NH_ * N_ * HD];
__device__ __half g_k[(size_t)NWIN * NH_ * N_ * HD];
__device__ __half g_v[(size_t)NWIN * NH_ * N_ * HD];
__device__ __half g_rpbh[(size_t)NH_ * N_ * RLD];  // half, padded rows
__device__ __half g_ao[(size_t)M_ * C];          // attention output (proj input)

// ---------------------------------------------------------------------------
// prep kernels
// ---------------------------------------------------------------------------
__global__ void prep_w_kernel(const float* __restrict__ qkvw,
                              const float* __restrict__ projw,
                              const float* __restrict__ qb,
                              const float* __restrict__ vb) {
  int g = blockIdx.x * 256 + threadIdx.x;
  if (g < 2304 * 768) g_wqkv[g] = __float2half(qkvw[g]);
  if (g < 768 * 768)  g_wproj[g] = __float2half(projw[g]);
  if (g < 2304) g_bqkv[g] = (g < 768) ? qb[g] : ((g < 1536) ? 0.0f : vb[g - 1536]);
}

__global__ void rpb_kernel(const float* __restrict__ table) {
  int g = blockIdx.x * 256 + threadIdx.x;
  if (g >= N_ * RLD) return;
  int a = g / RLD, b = g - a * RLD;
  if (b >= N_) {
#pragma unroll
    for (int hh = 0; hh < NH_; hh++)
      g_rpbh[(size_t)hh * N_ * RLD + g] = __float2half(0.0f);
    return;
  }
  int i1 = a / WS_, j1 = a - i1 * WS_;
  int i2 = b / WS_, j2 = b - i2 * WS_;
  int idx = (i1 - i2 + WS_ - 1) * (2 * WS_ - 1) + (j1 - j2 + WS_ - 1);
#pragma unroll
  for (int hh = 0; hh < NH_; hh++)
    g_rpbh[(size_t)hh * N_ * RLD + g] = __float2half(table[idx * NH_ + hh]);
}

// x [B, H*W, C] fp32 -> g_xh [win*196, C] fp16 (window partition gather fused)
__global__ void convx_kernel(const float* __restrict__ x) {
  int g = blockIdx.x * 256 + threadIdx.x;
  int m = g / 96, kk = g - m * 96;
  int w = m / N_, n = m - w * N_;
  int b = w >> 4, wr = w & 15, wh = wr >> 2, ww = wr & 3;
  int ii = n / WS_, jj = n - ii * WS_;
  size_t xr = (size_t)b * (HH * WWp) + (size_t)(wh * WS_ + ii) * WWp + (ww * WS_ + jj);
  const float4* src = (const float4*)(x + xr * C + kk * 8);
  float4 v0 = src[0], v1 = src[1];
  union { int4 i4; __half2 h2v[4]; } o;
  o.h2v[0] = __floats2half2_rn(v0.x, v0.y);
  o.h2v[1] = __floats2half2_rn(v0.z, v0.w);
  o.h2v[2] = __floats2half2_rn(v1.x, v1.y);
  o.h2v[3] = __floats2half2_rn(v1.z, v1.w);
  *(int4*)(g_xh + (size_t)m * C + kk * 8) = o.i4;
}

// ---------------------------------------------------------------------------
// WMMA GEMM v6: out[m, c] = sum_k A[m,k] * B[c,k] + bias[c]
// CTA 128 thr (4 warps, 2x2), tile 128x128, warp tile 64x64, K-step 64
// (12 iters, single barrier each), 3-stage cp.async, 2 CTAs/SM resident.
// MODE 0: QKV (A=g_xh, B=g_wqkv -> g_q/g_k/g_v, q scaled 0.125)
// MODE 1: proj (A=g_ao, B=g_wproj -> d_out image layout)
// ---------------------------------------------------------------------------
template <int MODE>
__global__ __launch_bounds__(128, 2) void gemm6_kernel(const float* __restrict__ bias_in,
                                                       float* __restrict__ out_f) {
  constexpr int BM = 128, BN = 128, BK = 64, S = 3;
  constexpr int LDA = 72, LDB = 72, LDE = 68;
  constexpr int NKT = KQ / BK;                       // 12
  constexpr int ABYTES = BM * LDA * 2;               // 18432
  constexpr int BBYTES = BN * LDB * 2;               // 18432
  constexpr int STG = ABYTES + BBYTES;               // 36864

  extern __shared__ __align__(16) char dsm[];
  float* ep = (float*)dsm;                           // epilogue reuse (128x68 f32)

  const __half* __restrict__ A  = (MODE == 0) ? g_xh : g_ao;
  const __half* __restrict__ Bw = (MODE == 0) ? g_wqkv : g_wproj;
  const int n0 = blockIdx.x * BN;
  const int m0 = blockIdx.y * BM;
  const int tid = threadIdx.x;
  const int warp = tid >> 5;
  const int wm = warp >> 1, wn = warp & 1;           // 2 x 2 warp grid

  wmma::fragment<wmma::accumulator, 16, 16, 16, float> acc[4][4];
#pragma unroll
  for (int i = 0; i < 4; i++)
#pragma unroll
    for (int j = 0; j < 4; j++) wmma::fill_fragment(acc[i][j], 0.0f);

  auto load_stage = [&](int kt) {
    const int slot = kt % S;
    char* abase = dsm + slot * STG;
    char* bbase = abase + ABYTES;
    const char* ag = (const char*)(A + (size_t)m0 * KQ + kt * BK);
    const char* bg = (const char*)(Bw + (size_t)n0 * KQ + kt * BK);
#pragma unroll
    for (int i = 0; i < 8; i++) {                    // A: 128 rows x 128B
      int q = tid + i * 128; int r = q >> 3, co = q & 7;
      asm volatile("{ .reg .u64 t; cvta.to.shared.u64 t, %0; .reg .u32 s; cvt.u32.u64 s, t;"
                   " cp.async.cg.shared.global [s], [%1], 16; }"
                   :: "l"(abase + r * (LDA * 2) + co * 16),
                      "l"(ag + (size_t)r * (KQ * 2) + co * 16) : "memory");
    }
#pragma unroll
    for (int i = 0; i < 8; i++) {                    // B: 128 rows x 128B
      int q = tid + i * 128; int r = q >> 3, co = q & 7;
      asm volatile("{ .reg .u64 t; cvta.to.shared.u64 t, %0; .reg .u32 s; cvt.u32.u64 s, t;"
                   " cp.async.cg.shared.global [s], [%1], 16; }"
                   :: "l"(bbase + r * (LDB * 2) + co * 16),
                      "l"(bg + (size_t)r * (KQ * 2) + co * 16) : "memory");
    }
    asm volatile("cp.async.commit_group;" ::: "memory");
  };

  load_stage(0);
  load_stage(1);

  for (int kt = 0; kt < NKT; kt++) {
    if (kt < NKT - 1) asm volatile("cp.async.wait_group 1;" ::: "memory");
    else              asm volatile("cp.async.wait_group 0;" ::: "memory");
    __syncthreads();                                 // the only barrier per iter
    if (kt + 2 < NKT) load_stage(kt + 2);

    const int slot = kt % S;
    const __half* sA = (const __half*)(dsm + slot * STG);
    const __half* sB = (const __half*)(dsm + slot * STG + ABYTES);
#pragma unroll
    for (int ks = 0; ks < 4; ks++) {
      wmma::fragment<wmma::matrix_a, 16, 16, 16, __half, wmma::row_major> af[4];
      wmma::fragment<wmma::matrix_b, 16, 16, 16, __half, wmma::col_major> bf[4];
#pragma unroll
      for (int i = 0; i < 4; i++)
        wmma::load_matrix_sync(af[i], &sA[(wm * 64 + i * 16) * LDA + ks * 16], LDA);
#pragma unroll
      for (int j = 0; j < 4; j++)
        wmma::load_matrix_sync(bf[j], &sB[(wn * 64 + j * 16) * LDB + ks * 16], LDB);
#pragma unroll
      for (int i = 0; i < 4; i++)
#pragma unroll
        for (int j = 0; j < 4; j++)
          wmma::mma_sync(acc[i][j], af[i], bf[j], acc[i][j]);
    }
  }

  // epilogue: 2 phases of 64 cols through smem, fused bias + vectorized scatter
#pragma unroll 1
  for (int p = 0; p < 2; p++) {
    __syncthreads();
    if (wn == p) {
#pragma unroll
      for (int i = 0; i < 4; i++)
#pragma unroll
        for (int j = 0; j < 4; j++)
          wmma::store_matrix_sync(&ep[(wm * 64 + i * 16) * LDE + j * 16],
                                  acc[i][j], LDE, wmma::mem_row_major);
    }
    __syncthreads();
#pragma unroll 4
    for (int it = 0; it < 32; it++) {                // 128 rows x 32 pairs
      int idx = it * 128 + tid;
      int r = idx >> 5, ccp = idx & 31;
      int cc = ccp * 2;
      int m = m0 + r;
      int c = n0 + p * 64 + cc;
      float v0 = ep[r * LDE + cc];
      float v1 = ep[r * LDE + cc + 1];
      int w = m / N_, n = m - w * N_;
      if (MODE == 0) {
        v0 += g_bqkv[c];
        v1 += g_bqkv[c + 1];
        int sec = c / 768, cu = c - sec * 768;
        int h = cu >> 6, d = cu & 63;                // pair stays within one head
        __half* dst = ((sec == 0) ? g_q : (sec == 1) ? g_k : g_v) +
                      ((size_t)(w * NH_ + h) * N_ + n) * HD + d;
        float sc = (sec == 0) ? 0.125f : 1.0f;
        *(__half2*)dst = __floats2half2_rn(v0 * sc, v1 * sc);
      } else {
        v0 += bias_in[c];
        v1 += bias_in[c + 1];
        int b = w >> 4, wr = w & 15, wh = wr >> 2, ww = wr & 3;
        int ii = n / WS_, jj = n - ii * WS_;
        size_t xr = (size_t)b * (HH * WWp) + (size_t)(wh * WS_ + ii) * WWp + (ww * WS_ + jj);
        *(float2*)(out_f + xr * C + c) = make_float2(v0, v1);
      }
    }
  }
}

// ---------------------------------------------------------------------------
// attention v4: one block per (window, head, 64-row q chunk). The S->exp->P->PV
// chain is WARP-PRIVATE (each warp owns 16 rows), so only 2 block barriers per
// key-tile (protect + publish K/V/rpb). Q fragments hoisted out of the loop.
// ---------------------------------------------------------------------------
__global__ __launch_bounds__(128) void attn_kernel() {
  constexpr int LQ = 72, LK = 72, LV = 80, LS = 36, LP = 40, LO = 84;
  constexpr int KT = 32, NT = 7;
  constexpr int QBYTES = 64 * LQ * 2;                // 9216

  extern __shared__ __align__(16) char asmem[];
  __half* Qs = (__half*)asmem;
  char*   ub = asmem + QBYTES;
  __half* Ks = (__half*)ub;                          // 4608
  __half* Vs = (__half*)(ub + 4608);                 // 5120
  float*  Ss = (float*)(ub + 9728);                  // 9216 (rows warp-private)
  __half* Ps = (__half*)(ub + 18944);                // 5120 (rows warp-private)
  __half* Rt = (__half*)(ub + 24064);                // 4096 -> ub size 28160
  float*  Os = (float*)ub;                           // reuse (21504)

  const int qc = blockIdx.x, h = blockIdx.y, w = blockIdx.z;
  const int tid = threadIdx.x, warp = tid >> 5, lane = tid & 31;
  const size_t base = ((size_t)w * NH_ + h) * N_ * HD;
  const __half* Qg = g_q + base;
  const __half* Kg = g_k + base;
  const __half* Vg = g_v + base;
  const __half* Rg = g_rpbh + (size_t)h * N_ * RLD;

  // load Q chunk (64 rows, zero-pad past 196)
#pragma unroll
  for (int i = 0; i < 4; i++) {
    int p = tid + i * 128;
    int r = p >> 3, ko = (p & 7) << 3;
    int n = qc * 64 + r;
    int4 val = (n < N_) ? *(const int4*)(Qg + (size_t)n * HD + ko) : make_int4(0, 0, 0, 0);
    *(int4*)&Qs[r * LQ + ko] = val;
  }
  __syncthreads();

  // hoist Q fragments (loop-invariant)
  wmma::fragment<wmma::matrix_a, 16, 16, 16, __half, wmma::row_major> qa[4];
#pragma unroll
  for (int kk = 0; kk < 4; kk++)
    wmma::load_matrix_sync(qa[kk], &Qs[(warp * 16) * LQ + kk * 16], LQ);

  wmma::fragment<wmma::accumulator, 16, 16, 16, float> oacc[5];
#pragma unroll
  for (int c = 0; c < 5; c++) wmma::fill_fragment(oacc[c], 0.0f);

  for (int t = 0; t < NT; t++) {
    if (t > 0) __syncthreads();                      // barrier 1: protect K/V/Rt
    // K,V tiles (32 rows x 64)
#pragma unroll
    for (int i = 0; i < 2; i++) {
      int p = tid + i * 128;
      int r = p >> 3, ko = (p & 7) << 3;
      int jg = t * KT + r;
      int4 kv, vv;
      if (jg < N_) {
        kv = *(const int4*)(Kg + (size_t)jg * HD + ko);
        vv = *(const int4*)(Vg + (size_t)jg * HD + ko);
      } else { kv = make_int4(0, 0, 0, 0); vv = kv; }
      *(int4*)&Ks[r * LK + ko] = kv;
      *(int4*)&Vs[r * LV + ko] = vv;
    }
    // rpb tile: 64 rows x 32 halfs = 256 int4, coalesced
#pragma unroll
    for (int i = 0; i < 2; i++) {
      int p = tid + i * 128;
      int r = p >> 2, q4 = p & 3;
      int n = qc * 64 + r;
      int4 rv = (n < N_) ? *(const int4*)(Rg + (size_t)n * RLD + t * KT + q4 * 8)
                         : make_int4(0, 0, 0, 0);
      *(int4*)&Rt[r * KT + q4 * 8] = rv;
    }
    if (tid < KT) {
      int jg = t * KT + tid;
      __half one = __float2half(jg < N_ ? 1.0f : 0.0f);
#pragma unroll
      for (int co = 0; co < 16; co++)
        Vs[tid * LV + 64 + co] = (co == 0) ? one : __float2half(0.0f);
    }
    __syncthreads();                                 // barrier 2: publish K/V/Rt

    // ----- warp-private from here to end of tile -----
    // S = Q K^T (own 16 rows)
#pragma unroll
    for (int j = 0; j < 2; j++) {
      wmma::fragment<wmma::accumulator, 16, 16, 16, float> sacc;
      wmma::fill_fragment(sacc, 0.0f);
#pragma unroll
      for (int kk = 0; kk < 4; kk++) {
        wmma::fragment<wmma::matrix_b, 16, 16, 16, __half, wmma::col_major> kb;
        wmma::load_matrix_sync(kb, &Ks[(j * 16) * LK + kk * 16], LK);
        wmma::mma_sync(sacc, qa[kk], kb, sacc);
      }
      wmma::store_matrix_sync(&Ss[(warp * 16) * LS + j * 16], sacc, LS, wmma::mem_row_major);
    }
    __syncwarp();

    // P = exp(S + rpb) (own 16 rows; lane handles one column across rows)
#pragma unroll
    for (int i = 0; i < 16; i++) {
      int r = warp * 16 + i;
      int n = qc * 64 + r, jg = t * KT + lane;
      float val = 0.0f;
      if (n < N_ && jg < N_) {
        float s = Ss[r * LS + lane] + __half2float(Rt[r * KT + lane]);
        val = __expf(s);
      }
      Ps[r * LP + lane] = __float2half(val);
    }
    __syncwarp();

    // O += P V (own 16 rows; col frag 4 accumulates the row-sum normalizer)
    {
      wmma::fragment<wmma::matrix_a, 16, 16, 16, __half, wmma::row_major> pa[2];
#pragma unroll
      for (int kk = 0; kk < 2; kk++)
        wmma::load_matrix_sync(pa[kk], &Ps[(warp * 16) * LP + kk * 16], LP);
#pragma unroll
      for (int c = 0; c < 5; c++) {
#pragma unroll
        for (int kk = 0; kk < 2; kk++) {
          wmma::fragment<wmma::matrix_b, 16, 16, 16, __half, wmma::row_major> vb;
          wmma::load_matrix_sync(vb, &Vs[(kk * 16) * LV + c * 16], LV);
          wmma::mma_sync(oacc[c], pa[kk], vb, oacc[c]);
        }
      }
    }
  }

  // normalize + write
  __syncthreads();                                   // before Os overwrites ub
#pragma unroll
  for (int c = 0; c < 5; c++)
    wmma::store_matrix_sync(&Os[(warp * 16) * LO + c * 16], oacc[c], LO, wmma::mem_row_major);
  __syncthreads();
#pragma unroll
  for (int i = 0; i < 32; i++) {
    int idx = i * 128 + tid;
    int r = idx >> 6, d = idx & 63;
    int n = qc * 64 + r;
    if (n < N_) {
      float l = Os[r * LO + 64];
      float o = Os[r * LO + d] / l;
      g_ao[((size_t)w * N_ + n) * C + h * HD + d] = __float2half(o);
    }
  }
}

// ---------------------------------------------------------------------------
extern "C" void kernel_launch(void* const* d_in, const int* in_sizes, int n_in,
                              void* d_out, int out_size) {
  const float* x     = (const float*)d_in[0];
  const float* qkvw  = (const float*)d_in[1];
  const float* qb    = (const float*)d_in[2];
  const float* vb    = (const float*)d_in[3];
  const float* table = (const float*)d_in[4];
  const float* projw = (const float*)d_in[5];
  const float* projb = (const float*)d_in[6];
  float* out = (float*)d_out;
  (void)in_sizes; (void)n_in; (void)out_size;

  const int DSMEM_G = 3 * 36864;                     // 110592 (2 CTAs/SM)
  const int DSMEM_A = 9216 + 28160;                  // 37376 (6 CTAs/SM)
  cudaFuncSetAttribute(gemm6_kernel<0>, cudaFuncAttributeMaxDynamicSharedMemorySize, DSMEM_G);
  cudaFuncSetAttribute(gemm6_kernel<1>, cudaFuncAttributeMaxDynamicSharedMemorySize, DSMEM_G);
  cudaFuncSetAttribute(attn_kernel, cudaFuncAttributeMaxDynamicSharedMemorySize, DSMEM_A);

  prep_w_kernel<<<(2304 * 768) / 256, 256>>>(qkvw, projw, qb, vb);
  rpb_kernel<<<(N_ * RLD + 255) / 256, 256>>>(table);
  convx_kernel<<<(M_ * 96) / 256, 256>>>(x);
  gemm6_kernel<0><<<dim3(2304 / 128, M_ / 128), 128, DSMEM_G>>>(nullptr, nullptr);
  attn_kernel<<<dim3(4, NH_, NWIN), 128, DSMEM_A>>>();
  gemm6_kernel<1><<<dim3(768 / 128, M_ / 128), 128, DSMEM_G>>>(projb, out);
}

// round 9
// speedup vs baseline: 1.7387x; 1.1914x over previous
#include <cuda_runtime.h>
#include <cuda_fp16.h>
#include <mma.h>
#include <cstdint>

using namespace nvcuda;

// Problem constants (static shapes)
constexpr int HH   = 56;
constexpr int WWp  = 56;
constexpr int C    = 768;
constexpr int NH_  = 12;
constexpr int HD   = 64;
constexpr int WS_  = 14;
constexpr int N_   = 196;        // tokens per window
constexpr int NWIN = 256;        // 16 batch * 16 windows
constexpr int M_   = NWIN * N_;  // 50176 rows
constexpr int KQ   = 768;
constexpr int RLD  = 224;        // padded rpb row stride (halfs) = 7 tiles x 32

// -------- device scratch (allocation-free rule: __device__ globals) --------
__device__ __half g_xh[(size_t)M_ * C];          // window-ordered fp16 x
__device__ __half g_wqkv[2304 * 768];
__device__ __half g_wproj[768 * 768];
__device__ float  g_bqkv[2304];
__device__ __half g_q[(size_t)NWIN * NH_ * N_ * HD];
__device__ __half g_k[(size_t)NWIN * NH_ * N_ * HD];
__device__ __half g_v[(size_t)NWIN * NH_ * N_ * HD];
__device__ __half g_rpbh[(size_t)NH_ * N_ * RLD];  // half, padded cols
__device__ __half g_ao[(size_t)M_ * C];          // attention output (proj input)

// ---------------- raw-PTX helpers (all sm_80-level; safe on compute_103) ----
__device__ __forceinline__ uint32_t smem_u32(const void* p) {
  uint32_t a;
  asm("{ .reg .u64 t; cvta.to.shared.u64 t, %1; cvt.u32.u64 %0, t; }" : "=r"(a) : "l"(p));
  return a;
}
__device__ __forceinline__ void cpa16(uint32_t dst, const void* src, bool valid) {
  int sz = valid ? 16 : 0;
  asm volatile("cp.async.cg.shared.global [%0], [%1], 16, %2;"
               :: "r"(dst), "l"(src), "r"(sz) : "memory");
}
__device__ __forceinline__ void ldx4(uint32_t* r, uint32_t a) {
  asm volatile("ldmatrix.sync.aligned.m8n8.x4.shared.b16 {%0,%1,%2,%3}, [%4];"
               : "=r"(r[0]), "=r"(r[1]), "=r"(r[2]), "=r"(r[3]) : "r"(a));
}
__device__ __forceinline__ void ldx4t(uint32_t* r, uint32_t a) {
  asm volatile("ldmatrix.sync.aligned.m8n8.x4.trans.shared.b16 {%0,%1,%2,%3}, [%4];"
               : "=r"(r[0]), "=r"(r[1]), "=r"(r[2]), "=r"(r[3]) : "r"(a));
}
__device__ __forceinline__ void ldx2(uint32_t* r, uint32_t a) {
  asm volatile("ldmatrix.sync.aligned.m8n8.x2.shared.b16 {%0,%1}, [%2];"
               : "=r"(r[0]), "=r"(r[1]) : "r"(a));
}
__device__ __forceinline__ void mma16816(float* d, const uint32_t* a, const uint32_t* b) {
  asm volatile("mma.sync.aligned.m16n8k16.row.col.f32.f16.f16.f32 "
               "{%0,%1,%2,%3}, {%4,%5,%6,%7}, {%8,%9}, {%0,%1,%2,%3};"
               : "+f"(d[0]), "+f"(d[1]), "+f"(d[2]), "+f"(d[3])
               : "r"(a[0]), "r"(a[1]), "r"(a[2]), "r"(a[3]), "r"(b[0]), "r"(b[1]));
}
__device__ __forceinline__ uint32_t packh2(float lo, float hi) {
  uint32_t p;
  asm("cvt.rn.f16x2.f32 %0, %1, %2;" : "=r"(p) : "f"(hi), "f"(lo));
  return p;
}

// ---------------------------------------------------------------------------
// prep kernels
// ---------------------------------------------------------------------------
__global__ void prep_w_kernel(const float* __restrict__ qkvw,
                              const float* __restrict__ projw,
                              const float* __restrict__ qb,
                              const float* __restrict__ vb) {
  int g = blockIdx.x * 256 + threadIdx.x;
  if (g < 2304 * 768) g_wqkv[g] = __float2half(qkvw[g]);
  if (g < 768 * 768)  g_wproj[g] = __float2half(projw[g]);
  if (g < 2304) g_bqkv[g] = (g < 768) ? qb[g] : ((g < 1536) ? 0.0f : vb[g - 1536]);
}

__global__ void rpb_kernel(const float* __restrict__ table) {
  int g = blockIdx.x * 256 + threadIdx.x;
  if (g >= N_ * RLD) return;
  int a = g / RLD, b = g - a * RLD;
  if (b >= N_) {
#pragma unroll
    for (int hh = 0; hh < NH_; hh++)
      g_rpbh[(size_t)hh * N_ * RLD + g] = __float2half(0.0f);
    return;
  }
  int i1 = a / WS_, j1 = a - i1 * WS_;
  int i2 = b / WS_, j2 = b - i2 * WS_;
  int idx = (i1 - i2 + WS_ - 1) * (2 * WS_ - 1) + (j1 - j2 + WS_ - 1);
#pragma unroll
  for (int hh = 0; hh < NH_; hh++)
    g_rpbh[(size_t)hh * N_ * RLD + g] = __float2half(table[idx * NH_ + hh]);
}

// x [B, H*W, C] fp32 -> g_xh [win*196, C] fp16 (window partition gather fused)
__global__ void convx_kernel(const float* __restrict__ x) {
  int g = blockIdx.x * 256 + threadIdx.x;
  int m = g / 96, kk = g - m * 96;
  int w = m / N_, n = m - w * N_;
  int b = w >> 4, wr = w & 15, wh = wr >> 2, ww = wr & 3;
  int ii = n / WS_, jj = n - ii * WS_;
  size_t xr = (size_t)b * (HH * WWp) + (size_t)(wh * WS_ + ii) * WWp + (ww * WS_ + jj);
  const float4* src = (const float4*)(x + xr * C + kk * 8);
  float4 v0 = src[0], v1 = src[1];
  union { int4 i4; __half2 h2v[4]; } o;
  o.h2v[0] = __floats2half2_rn(v0.x, v0.y);
  o.h2v[1] = __floats2half2_rn(v0.z, v0.w);
  o.h2v[2] = __floats2half2_rn(v1.x, v1.y);
  o.h2v[3] = __floats2half2_rn(v1.z, v1.w);
  *(int4*)(g_xh + (size_t)m * C + kk * 8) = o.i4;
}

// ---------------------------------------------------------------------------
// WMMA GEMM (R6 winner): CTA 128 thr, tile 128x128, warp tile 64x64, BK=32,
// 3-stage cp.async, single barrier per k-iter, 2 CTAs/SM resident.
// ---------------------------------------------------------------------------
template <int MODE>
__global__ __launch_bounds__(128, 2) void gemm5_kernel(const float* __restrict__ bias_in,
                                                       float* __restrict__ out_f) {
  constexpr int BM = 128, BN = 128, S = 3;
  constexpr int LDA = 40, LDB = 40, LDE = 68;
  constexpr int NKT = KQ / 32;
  constexpr int ABYTES = BM * LDA * 2;
  constexpr int STG = ABYTES + BN * LDB * 2;

  extern __shared__ __align__(16) char dsm[];
  float* ep = (float*)dsm;

  const __half* __restrict__ A  = (MODE == 0) ? g_xh : g_ao;
  const __half* __restrict__ Bw = (MODE == 0) ? g_wqkv : g_wproj;
  const int n0 = blockIdx.x * BN;
  const int m0 = blockIdx.y * BM;
  const int tid = threadIdx.x;
  const int warp = tid >> 5;
  const int wm = warp >> 1, wn = warp & 1;

  wmma::fragment<wmma::accumulator, 16, 16, 16, float> acc[4][4];
#pragma unroll
  for (int i = 0; i < 4; i++)
#pragma unroll
    for (int j = 0; j < 4; j++) wmma::fill_fragment(acc[i][j], 0.0f);

  auto load_stage = [&](int kt) {
    const int slot = kt % S;
    char* abase = dsm + slot * STG;
    char* bbase = abase + ABYTES;
    const char* ag = (const char*)(A + (size_t)m0 * KQ + kt * 32);
    const char* bg = (const char*)(Bw + (size_t)n0 * KQ + kt * 32);
#pragma unroll
    for (int i = 0; i < 4; i++) {
      int q = tid + i * 128; int r = q >> 2, co = q & 3;
      cpa16(smem_u32(abase + r * (LDA * 2) + co * 16),
            ag + (size_t)r * (KQ * 2) + co * 16, true);
    }
#pragma unroll
    for (int i = 0; i < 4; i++) {
      int q = tid + i * 128; int r = q >> 2, co = q & 3;
      cpa16(smem_u32(bbase + r * (LDB * 2) + co * 16),
            bg + (size_t)r * (KQ * 2) + co * 16, true);
    }
    asm volatile("cp.async.commit_group;" ::: "memory");
  };

  load_stage(0);
  load_stage(1);

  for (int kt = 0; kt < NKT; kt++) {
    if (kt < NKT - 1) asm volatile("cp.async.wait_group 1;" ::: "memory");
    else              asm volatile("cp.async.wait_group 0;" ::: "memory");
    __syncthreads();
    if (kt + 2 < NKT) load_stage(kt + 2);

    const int slot = kt % S;
    const __half* sA = (const __half*)(dsm + slot * STG);
    const __half* sB = (const __half*)(dsm + slot * STG + ABYTES);
#pragma unroll
    for (int ks = 0; ks < 2; ks++) {
      wmma::fragment<wmma::matrix_a, 16, 16, 16, __half, wmma::row_major> af[4];
      wmma::fragment<wmma::matrix_b, 16, 16, 16, __half, wmma::col_major> bf[4];
#pragma unroll
      for (int i = 0; i < 4; i++)
        wmma::load_matrix_sync(af[i], &sA[(wm * 64 + i * 16) * LDA + ks * 16], LDA);
#pragma unroll
      for (int j = 0; j < 4; j++)
        wmma::load_matrix_sync(bf[j], &sB[(wn * 64 + j * 16) * LDB + ks * 16], LDB);
#pragma unroll
      for (int i = 0; i < 4; i++)
#pragma unroll
        for (int j = 0; j < 4; j++)
          wmma::mma_sync(acc[i][j], af[i], bf[j], acc[i][j]);
    }
  }

#pragma unroll 1
  for (int p = 0; p < 2; p++) {
    __syncthreads();
    if (wn == p) {
#pragma unroll
      for (int i = 0; i < 4; i++)
#pragma unroll
        for (int j = 0; j < 4; j++)
          wmma::store_matrix_sync(&ep[(wm * 64 + i * 16) * LDE + j * 16],
                                  acc[i][j], LDE, wmma::mem_row_major);
    }
    __syncthreads();
#pragma unroll 4
    for (int it = 0; it < 32; it++) {
      int idx = it * 128 + tid;
      int r = idx >> 5, ccp = idx & 31;
      int cc = ccp * 2;
      int m = m0 + r;
      int c = n0 + p * 64 + cc;
      float v0 = ep[r * LDE + cc];
      float v1 = ep[r * LDE + cc + 1];
      int w = m / N_, n = m - w * N_;
      if (MODE == 0) {
        v0 += g_bqkv[c];
        v1 += g_bqkv[c + 1];
        int sec = c / 768, cu = c - sec * 768;
        int h = cu >> 6, d = cu & 63;
        __half* dst = ((sec == 0) ? g_q : (sec == 1) ? g_k : g_v) +
                      ((size_t)(w * NH_ + h) * N_ + n) * HD + d;
        float sc = (sec == 0) ? 0.125f : 1.0f;
        *(__half2*)dst = __floats2half2_rn(v0 * sc, v1 * sc);
      } else {
        v0 += bias_in[c];
        v1 += bias_in[c + 1];
        int b = w >> 4, wr = w & 15, wh = wr >> 2, ww = wr & 3;
        int ii = n / WS_, jj = n - ii * WS_;
        size_t xr = (size_t)b * (HH * WWp) + (size_t)(wh * WS_ + ii) * WWp + (ww * WS_ + jj);
        *(float2*)(out_f + xr * C + c) = make_float2(v0, v1);
      }
    }
  }
}

// ---------------------------------------------------------------------------
// attention v5b: register-resident flash-attention with raw mma.m16n8k16.
// One block per (window, head): 256 thr, 8 warps x 32 q-rows = 256 rows
// (rows >= 196 zero-filled and discarded). K/V/rpb streamed in 32-key tiles,
// 3-stage cp.async (zfill-guarded), ONE barrier per tile. S never touches
// smem: QK^T C-frag -> exp in regs -> f16x2 pack (== PV A-frag layout) ->
// PV mma. Row sums accumulate in f32 registers.
// FIX vs R8: Q and rpb smem regions sized for 256 rows (was 224 -> smem OOB).
// ---------------------------------------------------------------------------
__global__ __launch_bounds__(256, 1) void attn_kernel() {
  constexpr int KT = 32, NT = 7;
  constexpr int QR  = 256;                      // q rows covered by 8 warps
  constexpr int LR  = 40;                       // halfs per rpb smem row
  constexpr int LQB = 144;                      // K/V/Q smem row bytes (72 halfs)
  constexpr int KBYTES = KT * LQB;              // 4608
  constexpr int RBYTES = QR * LR * 2;           // 20480
  constexpr int STGB = 2 * KBYTES + RBYTES;     // 29696
  constexpr int QOFF = 3 * STGB;                // 89088

  extern __shared__ __align__(16) char asm_[];
  const uint32_t smb = smem_u32(asm_);

  const int h = blockIdx.x, w = blockIdx.y;
  const int tid = threadIdx.x, warp = tid >> 5, lane = tid & 31;
  const int tig = lane & 3, tq = lane >> 2;

  const size_t base = ((size_t)w * NH_ + h) * N_ * HD;
  const __half* Qg = g_q + base;
  const __half* Kg = g_k + base;
  const __half* Vg = g_v + base;
  const __half* Rg = g_rpbh + (size_t)h * N_ * RLD;

  // ---- Q into smem: 256 rows x 8 chunks = 2048 (zfill past N_) ----
#pragma unroll
  for (int i = 0; i < 8; i++) {
    int idx = tid + i * 256;
    int r = idx >> 3, c = idx & 7;
    cpa16(smb + QOFF + r * LQB + c * 16, Qg + (size_t)r * HD + c * 8, r < N_);
  }
  asm volatile("cp.async.commit_group;" ::: "memory");

  auto load_stage = [&](int t) {
    const uint32_t sb = smb + (t % 3) * STGB;
    {
      int r = tid >> 3, c = tid & 7;            // K,V: 32 rows x 8 chunks
      int jg = t * KT + r;
      cpa16(sb + r * LQB + c * 16, Kg + (size_t)jg * HD + c * 8, jg < N_);
      cpa16(sb + KBYTES + r * LQB + c * 16, Vg + (size_t)jg * HD + c * 8, jg < N_);
    }
#pragma unroll
    for (int i = 0; i < 4; i++) {               // rpb: 256 rows x 4 chunks = 1024
      int idx = tid + i * 256;
      int r = idx >> 2, c = idx & 3;
      cpa16(sb + 2 * KBYTES + r * (LR * 2) + c * 16,
            Rg + (size_t)r * RLD + t * KT + c * 8, r < N_);
    }
    asm volatile("cp.async.commit_group;" ::: "memory");
  };

  load_stage(0);
  load_stage(1);

  // wait for Q (allow the 2 stage groups outstanding), load Q fragments
  asm volatile("cp.async.wait_group 2;" ::: "memory");
  __syncthreads();
  uint32_t qa[2][4][4];
#pragma unroll
  for (int g = 0; g < 2; g++)
#pragma unroll
    for (int kk = 0; kk < 4; kk++) {
      uint32_t addr = smb + QOFF + (warp * 32 + g * 16 + (lane & 15)) * LQB +
                      (kk * 16 + ((lane >> 4) << 3)) * 2;
      ldx4(qa[g][kk], addr);
    }

  float oacc[2][8][4];
#pragma unroll
  for (int g = 0; g < 2; g++)
#pragma unroll
    for (int d = 0; d < 8; d++)
#pragma unroll
      for (int i = 0; i < 4; i++) oacc[g][d][i] = 0.0f;
  float rsum[2][2] = {{0.0f, 0.0f}, {0.0f, 0.0f}};

  for (int t = 0; t < NT; t++) {
    if (t < NT - 1) asm volatile("cp.async.wait_group 1;" ::: "memory");
    else            asm volatile("cp.async.wait_group 0;" ::: "memory");
    __syncthreads();
    if (t + 2 < NT) load_stage(t + 2);

    const uint32_t sb = smb + (t % 3) * STGB;
    const char* rb = asm_ + (t % 3) * STGB + 2 * KBYTES;

    // ---- S = Q K^T, exp, pack (all register-resident) ----
    uint32_t pa[2][2][4];
#pragma unroll
    for (int nb = 0; nb < 4; nb++) {
      float s0[4] = {0, 0, 0, 0}, s1[4] = {0, 0, 0, 0};
#pragma unroll
      for (int kk = 0; kk < 4; kk++) {
        uint32_t kf2[2];
        uint32_t ka = sb + (nb * 8 + (lane & 7)) * LQB +
                      (kk * 16 + (((lane >> 3) & 1) << 3)) * 2;
        ldx2(kf2, ka);
        mma16816(s0, qa[0][kk], kf2);
        mma16816(s1, qa[1][kk], kf2);
      }
      const int j0 = t * KT + nb * 8 + 2 * tig;
      const bool jv = (j0 < N_);
      const int cb = (nb * 8 + 2 * tig) * 2;    // rpb col byte offset
#pragma unroll
      for (int g = 0; g < 2; g++) {
        const float* sg = (g == 0) ? s0 : s1;
        int rlo = warp * 32 + g * 16 + tq;
        float e0 = 0, e1 = 0, e2 = 0, e3 = 0;
        if (jv) {
          float2 fl = __half22float2(*(const __half2*)(rb + rlo * (LR * 2) + cb));
          float2 fh = __half22float2(*(const __half2*)(rb + (rlo + 8) * (LR * 2) + cb));
          e0 = __expf(sg[0] + fl.x);
          e1 = __expf(sg[1] + fl.y);
          e2 = __expf(sg[2] + fh.x);
          e3 = __expf(sg[3] + fh.y);
        }
        rsum[g][0] += e0 + e1;
        rsum[g][1] += e2 + e3;
        pa[g][nb >> 1][(nb & 1) * 2 + 0] = packh2(e0, e1);
        pa[g][nb >> 1][(nb & 1) * 2 + 1] = packh2(e2, e3);
      }
    }

    // ---- O += P V ----
#pragma unroll
    for (int kb = 0; kb < 2; kb++)
#pragma unroll
      for (int dh = 0; dh < 4; dh++) {
        uint32_t vt[4];
        uint32_t va = sb + KBYTES + (kb * 16 + (lane & 15)) * LQB +
                      (dh * 16 + ((lane >> 4) << 3)) * 2;
        ldx4t(vt, va);
        mma16816(oacc[0][2 * dh],     pa[0][kb], vt + 0);
        mma16816(oacc[0][2 * dh + 1], pa[0][kb], vt + 2);
        mma16816(oacc[1][2 * dh],     pa[1][kb], vt + 0);
        mma16816(oacc[1][2 * dh + 1], pa[1][kb], vt + 2);
      }
  }

  // ---- normalize + write ----
#pragma unroll
  for (int g = 0; g < 2; g++) {
    float slo = rsum[g][0];
    slo += __shfl_xor_sync(0xFFFFFFFFu, slo, 1);
    slo += __shfl_xor_sync(0xFFFFFFFFu, slo, 2);
    float shi = rsum[g][1];
    shi += __shfl_xor_sync(0xFFFFFFFFu, shi, 1);
    shi += __shfl_xor_sync(0xFFFFFFFFu, shi, 2);
    float ilo = 1.0f / slo, ihi = 1.0f / shi;
    int nlo = warp * 32 + g * 16 + tq;
    int nhi = nlo + 8;
    __half* rowlo = g_ao + ((size_t)w * N_ + nlo) * C + h * HD;
    __half* rowhi = g_ao + ((size_t)w * N_ + nhi) * C + h * HD;
#pragma unroll
    for (int db = 0; db < 8; db++) {
      int col = db * 8 + 2 * tig;
      if (nlo < N_)
        *(__half2*)(rowlo + col) =
            __floats2half2_rn(oacc[g][db][0] * ilo, oacc[g][db][1] * ilo);
      if (nhi < N_)
        *(__half2*)(rowhi + col) =
            __floats2half2_rn(oacc[g][db][2] * ihi, oacc[g][db][3] * ihi);
    }
  }
}

// ---------------------------------------------------------------------------
extern "C" void kernel_launch(void* const* d_in, const int* in_sizes, int n_in,
                              void* d_out, int out_size) {
  const float* x     = (const float*)d_in[0];
  const float* qkvw  = (const float*)d_in[1];
  const float* qb    = (const float*)d_in[2];
  const float* vb    = (const float*)d_in[3];
  const float* table = (const float*)d_in[4];
  const float* projw = (const float*)d_in[5];
  const float* projb = (const float*)d_in[6];
  float* out = (float*)d_out;
  (void)in_sizes; (void)n_in; (void)out_size;

  const int DSMEM_G = 3 * 20480;                     // 61440
  const int DSMEM_A = 3 * 29696 + 256 * 144;         // 89088 + 36864 = 125952
  cudaFuncSetAttribute(gemm5_kernel<0>, cudaFuncAttributeMaxDynamicSharedMemorySize, DSMEM_G);
  cudaFuncSetAttribute(gemm5_kernel<1>, cudaFuncAttributeMaxDynamicSharedMemorySize, DSMEM_G);
  cudaFuncSetAttribute(attn_kernel, cudaFuncAttributeMaxDynamicSharedMemorySize, DSMEM_A);

  prep_w_kernel<<<(2304 * 768) / 256, 256>>>(qkvw, projw, qb, vb);
  rpb_kernel<<<(N_ * RLD + 255) / 256, 256>>>(table);
  convx_kernel<<<(M_ * 96) / 256, 256>>>(x);
  gemm5_kernel<0><<<dim3(2304 / 128, M_ / 128), 128, DSMEM_G>>>(nullptr, nullptr);
  attn_kernel<<<dim3(NH_, NWIN), 256, DSMEM_A>>>();
  gemm5_kernel<1><<<dim3(768 / 128, M_ / 128), 128, DSMEM_G>>>(projb, out);
}

// round 10
// speedup vs baseline: 1.8035x; 1.0373x over previous
#include <cuda_runtime.h>
#include <cuda_fp16.h>
#include <mma.h>
#include <cstdint>

using namespace nvcuda;

// Problem constants (static shapes)
constexpr int HH   = 56;
constexpr int WWp  = 56;
constexpr int C    = 768;
constexpr int NH_  = 12;
constexpr int HD   = 64;
constexpr int WS_  = 14;
constexpr int N_   = 196;        // tokens per window
constexpr int NWIN = 256;        // 16 batch * 16 windows
constexpr int M_   = NWIN * N_;  // 50176 rows
constexpr int KQ   = 768;
constexpr int RLD  = 224;        // padded rpb row stride (halfs) = 7 tiles x 32

// -------- device scratch (allocation-free rule: __device__ globals) --------
__device__ __half g_xh[(size_t)M_ * C];          // window-ordered fp16 x
__device__ __half g_wqkv[2304 * 768];
__device__ __half g_wproj[768 * 768];
__device__ float  g_bqkv[2304];
__device__ __half g_q[(size_t)NWIN * NH_ * N_ * HD];
__device__ __half g_k[(size_t)NWIN * NH_ * N_ * HD];
__device__ __half g_v[(size_t)NWIN * NH_ * N_ * HD];
__device__ __half g_rpbh[(size_t)NH_ * N_ * RLD];  // half, padded cols (1MB, L2-resident)
__device__ __half g_ao[(size_t)M_ * C];          // attention output (proj input)

// ---------------- raw-PTX helpers (all sm_80-level; safe on compute_103) ----
__device__ __forceinline__ uint32_t smem_u32(const void* p) {
  uint32_t a;
  asm("{ .reg .u64 t; cvta.to.shared.u64 t, %1; cvt.u32.u64 %0, t; }" : "=r"(a) : "l"(p));
  return a;
}
__device__ __forceinline__ void cpa16(uint32_t dst, const void* src, bool valid) {
  int sz = valid ? 16 : 0;
  asm volatile("cp.async.cg.shared.global [%0], [%1], 16, %2;"
               :: "r"(dst), "l"(src), "r"(sz) : "memory");
}
__device__ __forceinline__ void ldx4(uint32_t* r, uint32_t a) {
  asm volatile("ldmatrix.sync.aligned.m8n8.x4.shared.b16 {%0,%1,%2,%3}, [%4];"
               : "=r"(r[0]), "=r"(r[1]), "=r"(r[2]), "=r"(r[3]) : "r"(a));
}
__device__ __forceinline__ void ldx4t(uint32_t* r, uint32_t a) {
  asm volatile("ldmatrix.sync.aligned.m8n8.x4.trans.shared.b16 {%0,%1,%2,%3}, [%4];"
               : "=r"(r[0]), "=r"(r[1]), "=r"(r[2]), "=r"(r[3]) : "r"(a));
}
__device__ __forceinline__ void ldx2(uint32_t* r, uint32_t a) {
  asm volatile("ldmatrix.sync.aligned.m8n8.x2.shared.b16 {%0,%1}, [%2];"
               : "=r"(r[0]), "=r"(r[1]) : "r"(a));
}
__device__ __forceinline__ void mma16816(float* d, const uint32_t* a, const uint32_t* b) {
  asm volatile("mma.sync.aligned.m16n8k16.row.col.f32.f16.f16.f32 "
               "{%0,%1,%2,%3}, {%4,%5,%6,%7}, {%8,%9}, {%0,%1,%2,%3};"
               : "+f"(d[0]), "+f"(d[1]), "+f"(d[2]), "+f"(d[3])
               : "r"(a[0]), "r"(a[1]), "r"(a[2]), "r"(a[3]), "r"(b[0]), "r"(b[1]));
}
__device__ __forceinline__ uint32_t packh2(float lo, float hi) {
  uint32_t p;
  asm("cvt.rn.f16x2.f32 %0, %1, %2;" : "=r"(p) : "f"(hi), "f"(lo));
  return p;
}

// ---------------------------------------------------------------------------
// prep kernels
// ---------------------------------------------------------------------------
__global__ void prep_w_kernel(const float* __restrict__ qkvw,
                              const float* __restrict__ projw,
                              const float* __restrict__ qb,
                              const float* __restrict__ vb) {
  int g = blockIdx.x * 256 + threadIdx.x;
  if (g < 2304 * 768) g_wqkv[g] = __float2half(qkvw[g]);
  if (g < 768 * 768)  g_wproj[g] = __float2half(projw[g]);
  if (g < 2304) g_bqkv[g] = (g < 768) ? qb[g] : ((g < 1536) ? 0.0f : vb[g - 1536]);
}

__global__ void rpb_kernel(const float* __restrict__ table) {
  int g = blockIdx.x * 256 + threadIdx.x;
  if (g >= N_ * RLD) return;
  int a = g / RLD, b = g - a * RLD;
  if (b >= N_) {
#pragma unroll
    for (int hh = 0; hh < NH_; hh++)
      g_rpbh[(size_t)hh * N_ * RLD + g] = __float2half(0.0f);
    return;
  }
  int i1 = a / WS_, j1 = a - i1 * WS_;
  int i2 = b / WS_, j2 = b - i2 * WS_;
  int idx = (i1 - i2 + WS_ - 1) * (2 * WS_ - 1) + (j1 - j2 + WS_ - 1);
#pragma unroll
  for (int hh = 0; hh < NH_; hh++)
    g_rpbh[(size_t)hh * N_ * RLD + g] = __float2half(table[idx * NH_ + hh]);
}

// x [B, H*W, C] fp32 -> g_xh [win*196, C] fp16 (window partition gather fused)
__global__ void convx_kernel(const float* __restrict__ x) {
  int g = blockIdx.x * 256 + threadIdx.x;
  int m = g / 96, kk = g - m * 96;
  int w = m / N_, n = m - w * N_;
  int b = w >> 4, wr = w & 15, wh = wr >> 2, ww = wr & 3;
  int ii = n / WS_, jj = n - ii * WS_;
  size_t xr = (size_t)b * (HH * WWp) + (size_t)(wh * WS_ + ii) * WWp + (ww * WS_ + jj);
  const float4* src = (const float4*)(x + xr * C + kk * 8);
  float4 v0 = src[0], v1 = src[1];
  union { int4 i4; __half2 h2v[4]; } o;
  o.h2v[0] = __floats2half2_rn(v0.x, v0.y);
  o.h2v[1] = __floats2half2_rn(v0.z, v0.w);
  o.h2v[2] = __floats2half2_rn(v1.x, v1.y);
  o.h2v[3] = __floats2half2_rn(v1.z, v1.w);
  *(int4*)(g_xh + (size_t)m * C + kk * 8) = o.i4;
}

// ---------------------------------------------------------------------------
// WMMA GEMM (R6 winner): CTA 128 thr, tile 128x128, warp tile 64x64, BK=32,
// 3-stage cp.async, single barrier per k-iter, 2 CTAs/SM resident.
// ---------------------------------------------------------------------------
template <int MODE>
__global__ __launch_bounds__(128, 2) void gemm5_kernel(const float* __restrict__ bias_in,
                                                       float* __restrict__ out_f) {
  constexpr int BM = 128, BN = 128, S = 3;
  constexpr int LDA = 40, LDB = 40, LDE = 68;
  constexpr int NKT = KQ / 32;
  constexpr int ABYTES = BM * LDA * 2;
  constexpr int STG = ABYTES + BN * LDB * 2;

  extern __shared__ __align__(16) char dsm[];
  float* ep = (float*)dsm;

  const __half* __restrict__ A  = (MODE == 0) ? g_xh : g_ao;
  const __half* __restrict__ Bw = (MODE == 0) ? g_wqkv : g_wproj;
  const int n0 = blockIdx.x * BN;
  const int m0 = blockIdx.y * BM;
  const int tid = threadIdx.x;
  const int warp = tid >> 5;
  const int wm = warp >> 1, wn = warp & 1;

  wmma::fragment<wmma::accumulator, 16, 16, 16, float> acc[4][4];
#pragma unroll
  for (int i = 0; i < 4; i++)
#pragma unroll
    for (int j = 0; j < 4; j++) wmma::fill_fragment(acc[i][j], 0.0f);

  auto load_stage = [&](int kt) {
    const int slot = kt % S;
    char* abase = dsm + slot * STG;
    char* bbase = abase + ABYTES;
    const char* ag = (const char*)(A + (size_t)m0 * KQ + kt * 32);
    const char* bg = (const char*)(Bw + (size_t)n0 * KQ + kt * 32);
#pragma unroll
    for (int i = 0; i < 4; i++) {
      int q = tid + i * 128; int r = q >> 2, co = q & 3;
      cpa16(smem_u32(abase + r * (LDA * 2) + co * 16),
            ag + (size_t)r * (KQ * 2) + co * 16, true);
    }
#pragma unroll
    for (int i = 0; i < 4; i++) {
      int q = tid + i * 128; int r = q >> 2, co = q & 3;
      cpa16(smem_u32(bbase + r * (LDB * 2) + co * 16),
            bg + (size_t)r * (KQ * 2) + co * 16, true);
    }
    asm volatile("cp.async.commit_group;" ::: "memory");
  };

  load_stage(0);
  load_stage(1);

  for (int kt = 0; kt < NKT; kt++) {
    if (kt < NKT - 1) asm volatile("cp.async.wait_group 1;" ::: "memory");
    else              asm volatile("cp.async.wait_group 0;" ::: "memory");
    __syncthreads();
    if (kt + 2 < NKT) load_stage(kt + 2);

    const int slot = kt % S;
    const __half* sA = (const __half*)(dsm + slot * STG);
    const __half* sB = (const __half*)(dsm + slot * STG + ABYTES);
#pragma unroll
    for (int ks = 0; ks < 2; ks++) {
      wmma::fragment<wmma::matrix_a, 16, 16, 16, __half, wmma::row_major> af[4];
      wmma::fragment<wmma::matrix_b, 16, 16, 16, __half, wmma::col_major> bf[4];
#pragma unroll
      for (int i = 0; i < 4; i++)
        wmma::load_matrix_sync(af[i], &sA[(wm * 64 + i * 16) * LDA + ks * 16], LDA);
#pragma unroll
      for (int j = 0; j < 4; j++)
        wmma::load_matrix_sync(bf[j], &sB[(wn * 64 + j * 16) * LDB + ks * 16], LDB);
#pragma unroll
      for (int i = 0; i < 4; i++)
#pragma unroll
        for (int j = 0; j < 4; j++)
          wmma::mma_sync(acc[i][j], af[i], bf[j], acc[i][j]);
    }
  }

#pragma unroll 1
  for (int p = 0; p < 2; p++) {
    __syncthreads();
    if (wn == p) {
#pragma unroll
      for (int i = 0; i < 4; i++)
#pragma unroll
        for (int j = 0; j < 4; j++)
          wmma::store_matrix_sync(&ep[(wm * 64 + i * 16) * LDE + j * 16],
                                  acc[i][j], LDE, wmma::mem_row_major);
    }
    __syncthreads();
#pragma unroll 4
    for (int it = 0; it < 32; it++) {
      int idx = it * 128 + tid;
      int r = idx >> 5, ccp = idx & 31;
      int cc = ccp * 2;
      int m = m0 + r;
      int c = n0 + p * 64 + cc;
      float v0 = ep[r * LDE + cc];
      float v1 = ep[r * LDE + cc + 1];
      int w = m / N_, n = m - w * N_;
      if (MODE == 0) {
        v0 += g_bqkv[c];
        v1 += g_bqkv[c + 1];
        int sec = c / 768, cu = c - sec * 768;
        int h = cu >> 6, d = cu & 63;
        __half* dst = ((sec == 0) ? g_q : (sec == 1) ? g_k : g_v) +
                      ((size_t)(w * NH_ + h) * N_ + n) * HD + d;
        float sc = (sec == 0) ? 0.125f : 1.0f;
        *(__half2*)dst = __floats2half2_rn(v0 * sc, v1 * sc);
      } else {
        v0 += bias_in[c];
        v1 += bias_in[c + 1];
        int b = w >> 4, wr = w & 15, wh = wr >> 2, ww = wr & 3;
        int ii = n / WS_, jj = n - ii * WS_;
        size_t xr = (size_t)b * (HH * WWp) + (size_t)(wh * WS_ + ii) * WWp + (ww * WS_ + jj);
        *(float2*)(out_f + xr * C + c) = make_float2(v0, v1);
      }
    }
  }
}

// ---------------------------------------------------------------------------
// attention v6: 128-thread CTAs (4 warps x 32 q-rows), 2 q-blocks per
// (window, head) -> smaller CTAs with INDEPENDENT barriers, 2-3 resident/SM.
// rpb staging removed: g_rpbh is L2-resident (1MB); each thread prefetches
// its 16 half2 rpb values per tile into registers, hidden under S compute.
// Stage = K+V only (9216B); smem/CTA = 46080B.
// ---------------------------------------------------------------------------
__global__ __launch_bounds__(128) void attn_kernel() {
  constexpr int KT = 32, NT = 7;
  constexpr int QR  = 128;                      // q rows per CTA (4 warps x 32)
  constexpr int LQB = 144;                      // K/V/Q smem row bytes (72 halfs)
  constexpr int KBYTES = KT * LQB;              // 4608
  constexpr int STGB = 2 * KBYTES;              // 9216 (K + V)
  constexpr int QOFF = 3 * STGB;                // 27648

  extern __shared__ __align__(16) char asm_[];
  const uint32_t smb = smem_u32(asm_);

  const int h = blockIdx.x, w = blockIdx.y, qc = blockIdx.z;
  const int tid = threadIdx.x, warp = tid >> 5, lane = tid & 31;
  const int tig = lane & 3, tq = lane >> 2;
  const int row0 = qc * QR;                     // global q-row base for this CTA

  const size_t base = ((size_t)w * NH_ + h) * N_ * HD;
  const __half* Qg = g_q + base;
  const __half* Kg = g_k + base;
  const __half* Vg = g_v + base;
  const __half* Rg = g_rpbh + (size_t)h * N_ * RLD;

  // ---- Q into smem: 128 rows x 8 chunks = 1024 (zfill past N_) ----
#pragma unroll
  for (int i = 0; i < 8; i++) {
    int idx = tid + i * 128;
    int r = idx >> 3, c = idx & 7;
    int n = row0 + r;
    cpa16(smb + QOFF + r * LQB + c * 16, Qg + (size_t)n * HD + c * 8, n < N_);
  }
  asm volatile("cp.async.commit_group;" ::: "memory");

  auto load_stage = [&](int t) {
    const uint32_t sb = smb + (t % 3) * STGB;
#pragma unroll
    for (int i = 0; i < 2; i++) {               // K,V: 32 rows x 8 chunks = 256 each
      int idx = tid + i * 128;
      int r = idx >> 3, c = idx & 7;
      int jg = t * KT + r;
      cpa16(sb + r * LQB + c * 16, Kg + (size_t)jg * HD + c * 8, jg < N_);
      cpa16(sb + KBYTES + r * LQB + c * 16, Vg + (size_t)jg * HD + c * 8, jg < N_);
    }
    asm volatile("cp.async.commit_group;" ::: "memory");
  };

  load_stage(0);
  load_stage(1);

  // wait for Q (allow the 2 stage groups outstanding), load Q fragments
  asm volatile("cp.async.wait_group 2;" ::: "memory");
  __syncthreads();
  uint32_t qa[2][4][4];
#pragma unroll
  for (int g = 0; g < 2; g++)
#pragma unroll
    for (int kk = 0; kk < 4; kk++) {
      uint32_t addr = smb + QOFF + (warp * 32 + g * 16 + (lane & 15)) * LQB +
                      (kk * 16 + ((lane >> 4) << 3)) * 2;
      ldx4(qa[g][kk], addr);
    }

  float oacc[2][8][4];
#pragma unroll
  for (int g = 0; g < 2; g++)
#pragma unroll
    for (int d = 0; d < 8; d++)
#pragma unroll
      for (int i = 0; i < 4; i++) oacc[g][d][i] = 0.0f;
  float rsum[2][2] = {{0.0f, 0.0f}, {0.0f, 0.0f}};

  for (int t = 0; t < NT; t++) {
    if (t < NT - 1) asm volatile("cp.async.wait_group 1;" ::: "memory");
    else            asm volatile("cp.async.wait_group 0;" ::: "memory");
    __syncthreads();
    if (t + 2 < NT) load_stage(t + 2);

    const uint32_t sb = smb + (t % 3) * STGB;

    // ---- rpb prefetch: 16 half2 directly from gmem (L2-resident) ----
    uint32_t rpre[2][2][4];
#pragma unroll
    for (int g = 0; g < 2; g++)
#pragma unroll
      for (int p2 = 0; p2 < 2; p2++) {
        int rr = row0 + warp * 32 + g * 16 + tq + p2 * 8;
        const __half* rrow = Rg + (size_t)rr * RLD + t * KT + 2 * tig;
#pragma unroll
        for (int nb = 0; nb < 4; nb++)
          rpre[g][p2][nb] = (rr < N_) ? *(const uint32_t*)(rrow + nb * 8) : 0u;
      }

    // ---- S = Q K^T, exp, pack (all register-resident) ----
    uint32_t pa[2][2][4];
#pragma unroll
    for (int nb = 0; nb < 4; nb++) {
      float s0[4] = {0, 0, 0, 0}, s1[4] = {0, 0, 0, 0};
#pragma unroll
      for (int kk = 0; kk < 4; kk++) {
        uint32_t kf2[2];
        uint32_t ka = sb + (nb * 8 + (lane & 7)) * LQB +
                      (kk * 16 + (((lane >> 3) & 1) << 3)) * 2;
        ldx2(kf2, ka);
        mma16816(s0, qa[0][kk], kf2);
        mma16816(s1, qa[1][kk], kf2);
      }
      const int j0 = t * KT + nb * 8 + 2 * tig;
      const bool jv = (j0 < N_);
#pragma unroll
      for (int g = 0; g < 2; g++) {
        const float* sg = (g == 0) ? s0 : s1;
        float e0 = 0, e1 = 0, e2 = 0, e3 = 0;
        if (jv) {
          float2 fl = __half22float2(*(const __half2*)&rpre[g][0][nb]);
          float2 fh = __half22float2(*(const __half2*)&rpre[g][1][nb]);
          e0 = __expf(sg[0] + fl.x);
          e1 = __expf(sg[1] + fl.y);
          e2 = __expf(sg[2] + fh.x);
          e3 = __expf(sg[3] + fh.y);
        }
        rsum[g][0] += e0 + e1;
        rsum[g][1] += e2 + e3;
        pa[g][nb >> 1][(nb & 1) * 2 + 0] = packh2(e0, e1);
        pa[g][nb >> 1][(nb & 1) * 2 + 1] = packh2(e2, e3);
      }
    }

    // ---- O += P V ----
#pragma unroll
    for (int kb = 0; kb < 2; kb++)
#pragma unroll
      for (int dh = 0; dh < 4; dh++) {
        uint32_t vt[4];
        uint32_t va = sb + KBYTES + (kb * 16 + (lane & 15)) * LQB +
                      (dh * 16 + ((lane >> 4) << 3)) * 2;
        ldx4t(vt, va);
        mma16816(oacc[0][2 * dh],     pa[0][kb], vt + 0);
        mma16816(oacc[0][2 * dh + 1], pa[0][kb], vt + 2);
        mma16816(oacc[1][2 * dh],     pa[1][kb], vt + 0);
        mma16816(oacc[1][2 * dh + 1], pa[1][kb], vt + 2);
      }
  }

  // ---- normalize + write ----
#pragma unroll
  for (int g = 0; g < 2; g++) {
    float slo = rsum[g][0];
    slo += __shfl_xor_sync(0xFFFFFFFFu, slo, 1);
    slo += __shfl_xor_sync(0xFFFFFFFFu, slo, 2);
    float shi = rsum[g][1];
    shi += __shfl_xor_sync(0xFFFFFFFFu, shi, 1);
    shi += __shfl_xor_sync(0xFFFFFFFFu, shi, 2);
    float ilo = 1.0f / slo, ihi = 1.0f / shi;
    int nlo = row0 + warp * 32 + g * 16 + tq;
    int nhi = nlo + 8;
    __half* rowlo = g_ao + ((size_t)w * N_ + nlo) * C + h * HD;
    __half* rowhi = g_ao + ((size_t)w * N_ + nhi) * C + h * HD;
#pragma unroll
    for (int db = 0; db < 8; db++) {
      int col = db * 8 + 2 * tig;
      if (nlo < N_)
        *(__half2*)(rowlo + col) =
            __floats2half2_rn(oacc[g][db][0] * ilo, oacc[g][db][1] * ilo);
      if (nhi < N_)
        *(__half2*)(rowhi + col) =
            __floats2half2_rn(oacc[g][db][2] * ihi, oacc[g][db][3] * ihi);
    }
  }
}

// ---------------------------------------------------------------------------
extern "C" void kernel_launch(void* const* d_in, const int* in_sizes, int n_in,
                              void* d_out, int out_size) {
  const float* x     = (const float*)d_in[0];
  const float* qkvw  = (const float*)d_in[1];
  const float* qb    = (const float*)d_in[2];
  const float* vb    = (const float*)d_in[3];
  const float* table = (const float*)d_in[4];
  const float* projw = (const float*)d_in[5];
  const float* projb = (const float*)d_in[6];
  float* out = (float*)d_out;
  (void)in_sizes; (void)n_in; (void)out_size;

  const int DSMEM_G = 3 * 20480;                     // 61440
  const int DSMEM_A = 3 * 9216 + 128 * 144;          // 27648 + 18432 = 46080
  cudaFuncSetAttribute(gemm5_kernel<0>, cudaFuncAttributeMaxDynamicSharedMemorySize, DSMEM_G);
  cudaFuncSetAttribute(gemm5_kernel<1>, cudaFuncAttributeMaxDynamicSharedMemorySize, DSMEM_G);
  cudaFuncSetAttribute(attn_kernel, cudaFuncAttributeMaxDynamicSharedMemorySize, DSMEM_A);

  prep_w_kernel<<<(2304 * 768) / 256, 256>>>(qkvw, projw, qb, vb);
  rpb_kernel<<<(N_ * RLD + 255) / 256, 256>>>(table);
  convx_kernel<<<(M_ * 96) / 256, 256>>>(x);
  gemm5_kernel<0><<<dim3(2304 / 128, M_ / 128), 128, DSMEM_G>>>(nullptr, nullptr);
  attn_kernel<<<dim3(NH_, NWIN, 2), 128, DSMEM_A>>>();
  gemm5_kernel<1><<<dim3(768 / 128, M_ / 128), 128, DSMEM_G>>>(projb, out);
}